// round 12
// baseline (speedup 1.0000x reference)
#include <cuda_runtime.h>
#include <cuda_bf16.h>
#include <cstdint>

#define BB 2
#define NN 384
#define DD 256
#define DDIRC 128
#define DSIMC 64
#define EPSF 1e-6f
#define DELTAF 1e-6f

// ---------------- scratch (static device globals; no allocations) ----------------
__device__ float g_q [BB*NN*DSIMC];
__device__ float g_k [BB*NN*DSIMC];
__device__ float g_qd[BB*NN*DDIRC];
__device__ float g_kd[BB*NN*DDIRC];
__device__ float g_s [BB*NN*NN];
__device__ float g_m [BB*NN];
__device__ double g_stats[BB*2];
__device__ __nv_bfloat16 g_vdt[DD*DDIRC];   // Vdt[d][r] = Vd[r][d], bf16

// ---------------- K0: zero stats + transpose/convert Vd ----------------
__global__ void k0_init(const float* __restrict__ Vd) {
    int idx = blockIdx.x*blockDim.x + threadIdx.x;
    if (idx < BB*2) g_stats[idx] = 0.0;
    for (int i = idx; i < DD*DDIRC; i += gridDim.x*blockDim.x) {
        int d = i / DDIRC, r = i % DDIRC;
        g_vdt[i] = __float2bfloat16(Vd[r*DD + d]);
    }
}

// ---------------- K1: projections q,k,qd,kd ----------------
__global__ void k1_proj(const float* __restrict__ t,
                        const float* __restrict__ Qd, const float* __restrict__ Kd,
                        const float* __restrict__ Qs, const float* __restrict__ Ks) {
    int b = blockIdx.y, n = blockIdx.x;
    __shared__ float ts[DD];
    int tid = threadIdx.x;                  // 384 threads
    if (tid < DD) ts[tid] = t[(b*NN+n)*DD + tid];
    __syncthreads();
    const float* W; int ld, col; float* outp;
    if (tid < 64)       { W = Qs; ld = DSIMC; col = tid;     outp = &g_q [(b*NN+n)*DSIMC + col]; }
    else if (tid < 128) { W = Ks; ld = DSIMC; col = tid-64;  outp = &g_k [(b*NN+n)*DSIMC + col]; }
    else if (tid < 256) { W = Qd; ld = DDIRC; col = tid-128; outp = &g_qd[(b*NN+n)*DDIRC + col]; }
    else                { W = Kd; ld = DDIRC; col = tid-256; outp = &g_kd[(b*NN+n)*DDIRC + col]; }
    float acc = 0.f;
    #pragma unroll 8
    for (int r = 0; r < DD; r++) acc += ts[r] * W[r*ld + col];
    *outp = acc;
}

// ---------------- K2: symmetrized s + off-diagonal sum / sumsq ----------------
__global__ void k2_sim() {
    int b = blockIdx.y, i = blockIdx.x, j = threadIdx.x;   // 384 threads
    __shared__ float qi[DSIMC], ki[DSIMC];
    __shared__ float red0[12], red1[12];
    if (j < DSIMC)        qi[j]       = g_q[(b*NN+i)*DSIMC + j];
    else if (j < 2*DSIMC) ki[j-DSIMC] = g_k[(b*NN+i)*DSIMC + (j-DSIMC)];
    __syncthreads();
    const float4* kj = (const float4*)&g_k[(b*NN+j)*DSIMC];
    const float4* qj = (const float4*)&g_q[(b*NN+j)*DSIMC];
    float acc = 0.f;
    #pragma unroll
    for (int r4 = 0; r4 < DSIMC/4; r4++) {
        float4 kv = kj[r4], qv = qj[r4];
        acc += qi[4*r4+0]*kv.x + qi[4*r4+1]*kv.y + qi[4*r4+2]*kv.z + qi[4*r4+3]*kv.w;
        acc += ki[4*r4+0]*qv.x + ki[4*r4+1]*qv.y + ki[4*r4+2]*qv.z + ki[4*r4+3]*qv.w;
    }
    float s = acc * 0.0625f;   // 0.5 / sqrt(64)
    g_s[(b*NN+i)*NN + j] = s;
    float sv = (j == i) ? 0.f : s;
    float s2 = sv * sv;
    #pragma unroll
    for (int o = 16; o; o >>= 1) {
        sv += __shfl_xor_sync(~0u, sv, o);
        s2 += __shfl_xor_sync(~0u, s2, o);
    }
    int w = j >> 5, l = j & 31;
    if (!l) { red0[w] = sv; red1[w] = s2; }
    __syncthreads();
    if (j == 0) {
        double a = 0, c = 0;
        for (int w2 = 0; w2 < 12; w2++) { a += (double)red0[w2]; c += (double)red1[w2]; }
        atomicAdd(&g_stats[b*2+0], a);
        atomicAdd(&g_stats[b*2+1], c);
    }
}

// ---------------- K3: per-row exp-sum -> m ----------------
__global__ void k3_m(const float* __restrict__ al, const float* __restrict__ bl) {
    int b = blockIdx.y, i = blockIdx.x, j = threadIdx.x;   // 384 threads
    __shared__ float red[12];
    const float cnt = (float)(NN*(NN-1));
    float mu  = (float)(g_stats[b*2+0] / cnt);
    float var = (float)(g_stats[b*2+1] / cnt) - mu*mu;
    float inv = rsqrtf(var + EPSF);
    float a = al[0], bv = bl[0];
    float s  = g_s[(b*NN+i)*NN + j];
    float ts = a * ((s - mu) * inv) + bv;
    float e  = expf(ts);   // GAMMA = 1
    #pragma unroll
    for (int o = 16; o; o >>= 1) e += __shfl_xor_sync(~0u, e, o);
    int w = j >> 5, l = j & 31;
    if (!l) red[w] = e;
    __syncthreads();
    if (j == 0) {
        float E = 0.f;
        for (int w2 = 0; w2 < 12; w2++) E += red[w2];
        g_m[b*NN+i] = 1.f / (E + EPSF);
    }
}

// ---------------- K5: heavy fused gate + aggregation ----------------
__global__ void __launch_bounds__(256) k5_heavy(
    const float* __restrict__ t, const float* __restrict__ al,
    const float* __restrict__ bl, float* __restrict__ outp)
{
    const int b = blockIdx.y, i = blockIdx.x;
    const int tid  = threadIdx.x;
    const int lane = tid & 31, wid = tid >> 5;
    const int T = lane & 3, grp = lane >> 2;

    __shared__ float sm_ti[DD];
    __shared__ float sm_qdi[DDIRC], sm_kdi[DDIRC];
    __shared__ float sm_alpha[NN];
    __shared__ __align__(16) __nv_bfloat16 sm_U[16*136];
    __shared__ float sm_t[16*260];
    __shared__ float sm_red[8];

    // ---- prologue loads ----
    if (tid < DD) sm_ti[tid] = t[(b*NN+i)*DD + tid];
    if (tid < DDIRC)        sm_qdi[tid]        = g_qd[(b*NN+i)*DDIRC + tid];
    else if (tid < 2*DDIRC) sm_kdi[tid-DDIRC]  = g_kd[(b*NN+i)*DDIRC + tid - DDIRC];

    // ---- alpha row in smem ----
    const float cnt = (float)(NN*(NN-1));
    float mu  = (float)(g_stats[b*2+0] / cnt);
    float var = (float)(g_stats[b*2+1] / cnt) - mu*mu;
    float inv = rsqrtf(var + EPSF);
    float aa = al[0], bv = bl[0];
    float rs = 0.f;
    for (int j = tid; j < NN; j += 256) {
        float s  = g_s[(b*NN+i)*NN + j];
        float ts = aa * ((s - mu) * inv) + bv;
        float A  = 1.f / (1.f + expf(-ts));
        float w  = A * g_m[b*NN + j];
        sm_alpha[j] = A * w;
        rs += w;                                // rowsum of w includes diagonal
    }
    #pragma unroll
    for (int o = 16; o; o >>= 1) rs += __shfl_xor_sync(~0u, rs, o);
    if (!lane) sm_red[wid] = rs;
    __syncthreads();
    float rstot = 0.f;
    #pragma unroll
    for (int w2 = 0; w2 < 8; w2++) rstot += sm_red[w2];
    float rinv = 1.f / (rstot + DELTAF);
    for (int j = tid; j < NN; j += 256)
        sm_alpha[j] = (j == i) ? 0.f : sm_alpha[j] * rinv;

    // ---- preload B fragments (Vd) into registers: breg[kc][f][2] ----
    uint32_t breg[8][4][2];
    const int warpD = wid * 32;
    #pragma unroll
    for (int kc = 0; kc < 8; kc++)
        #pragma unroll
        for (int f = 0; f < 4; f++) {
            int n = warpD + 8*f + grp;
            const __nv_bfloat16* base = &g_vdt[n*DDIRC + kc*16 + 2*T];
            breg[kc][f][0] = *(const uint32_t*)(base);
            breg[kc][f][1] = *(const uint32_t*)(base + 8);
        }

    float acc[4][2] = {};

    const int jj = tid >> 4;           // 0..15 (row within tile)
    const int rb = (tid & 15) * 8;     // U-build r base
    const int db = (tid & 15) * 16;    // t-tile d base

    for (int jt = 0; jt < NN/16; jt++) {
        const int j0 = jt * 16;
        __syncthreads();
        // ---- build U tile (bf16) + t tile (f32) in smem ----
        {
            int j = j0 + jj;
            const float4* kdj = (const float4*)&g_kd[(b*NN+j)*DDIRC + rb];
            const float4* qdj = (const float4*)&g_qd[(b*NN+j)*DDIRC + rb];
            float4 kv0 = kdj[0], kv1 = kdj[1];
            float4 qv0 = qdj[0], qv1 = qdj[1];
            float kd_[8] = {kv0.x,kv0.y,kv0.z,kv0.w,kv1.x,kv1.y,kv1.z,kv1.w};
            float qd_[8] = {qv0.x,qv0.y,qv0.z,qv0.w,qv1.x,qv1.y,qv1.z,qv1.w};
            float u[8];
            #pragma unroll
            for (int v = 0; v < 8; v++)
                u[v] = sm_qdi[rb+v]*kd_[v] - qd_[v]*sm_kdi[rb+v];
            __nv_bfloat162* dst = (__nv_bfloat162*)&sm_U[jj*136 + rb];
            #pragma unroll
            for (int p = 0; p < 4; p++)
                dst[p] = __floats2bfloat162_rn(u[2*p], u[2*p+1]);

            const float4* tj = (const float4*)&t[(b*NN+j)*DD + db];
            float4 t0 = tj[0], t1 = tj[1], t2 = tj[2], t3 = tj[3];
            float* td = &sm_t[jj*260 + db];
            *(float4*)(td+0)  = t0;  *(float4*)(td+4)  = t1;
            *(float4*)(td+8)  = t2;  *(float4*)(td+12) = t3;
        }
        __syncthreads();

        // ---- MMA: Delta tile (16 j x 32 d per warp) ----
        float c[4][4] = {};
        #pragma unroll
        for (int kc = 0; kc < 8; kc++) {
            const __nv_bfloat16* u0 = &sm_U[grp*136     + kc*16 + 2*T];
            const __nv_bfloat16* u1 = &sm_U[(grp+8)*136 + kc*16 + 2*T];
            uint32_t a0 = *(const uint32_t*)(u0);
            uint32_t a1 = *(const uint32_t*)(u1);
            uint32_t a2 = *(const uint32_t*)(u0 + 8);
            uint32_t a3 = *(const uint32_t*)(u1 + 8);
            #pragma unroll
            for (int f = 0; f < 4; f++)
                asm volatile(
                    "mma.sync.aligned.m16n8k16.row.col.f32.bf16.bf16.f32 "
                    "{%0,%1,%2,%3}, {%4,%5,%6,%7}, {%8,%9}, {%0,%1,%2,%3};"
                    : "+f"(c[f][0]), "+f"(c[f][1]), "+f"(c[f][2]), "+f"(c[f][3])
                    : "r"(a0), "r"(a1), "r"(a2), "r"(a3),
                      "r"(breg[kc][f][0]), "r"(breg[kc][f][1]));
        }

        // ---- epilogue: sigmoid, alpha, (t_i - t_j), accumulate over j ----
        float ar0 = sm_alpha[j0 + grp];
        float ar1 = sm_alpha[j0 + grp + 8];
        #pragma unroll
        for (int f = 0; f < 4; f++) {
            int d0 = warpD + 8*f + 2*T;
            float ti0 = sm_ti[d0], ti1 = sm_ti[d0+1];
            float tj00 = sm_t[grp*260 + d0],       tj01 = sm_t[grp*260 + d0 + 1];
            float tj10 = sm_t[(grp+8)*260 + d0],   tj11 = sm_t[(grp+8)*260 + d0 + 1];
            float g00 = 1.f/(1.f + __expf(-c[f][0]));   // row grp,   col d0
            float g01 = 1.f/(1.f + __expf(-c[f][1]));   // row grp,   col d0+1
            float g10 = 1.f/(1.f + __expf(-c[f][2]));   // row grp+8, col d0
            float g11 = 1.f/(1.f + __expf(-c[f][3]));   // row grp+8, col d0+1
            acc[f][0] += ar0*g00*(ti0 - tj00) + ar1*g10*(ti0 - tj10);
            acc[f][1] += ar0*g01*(ti1 - tj01) + ar1*g11*(ti1 - tj11);
        }
    }

    // ---- reduce over the 8 row-groups (lanes differing in grp bits) ----
    #pragma unroll
    for (int f = 0; f < 4; f++)
        #pragma unroll
        for (int e = 0; e < 2; e++) {
            float v = acc[f][e];
            v += __shfl_xor_sync(~0u, v, 4);
            v += __shfl_xor_sync(~0u, v, 8);
            v += __shfl_xor_sync(~0u, v, 16);
            acc[f][e] = v;
        }
    if (grp == 0) {
        #pragma unroll
        for (int f = 0; f < 4; f++) {
            int d0 = warpD + 8*f + 2*T;
            outp[(b*NN+i)*DD + d0]   = sm_ti[d0]   - acc[f][0];
            outp[(b*NN+i)*DD + d0+1] = sm_ti[d0+1] - acc[f][1];
        }
    }
}

// ---------------- launch ----------------
extern "C" void kernel_launch(void* const* d_in, const int* in_sizes, int n_in,
                              void* d_out, int out_size) {
    const float* t  = (const float*)d_in[0];
    const float* Qd = (const float*)d_in[1];
    const float* Kd = (const float*)d_in[2];
    const float* Vd = (const float*)d_in[3];
    const float* Qs = (const float*)d_in[4];
    const float* Ks = (const float*)d_in[5];
    const float* al = (const float*)d_in[6];
    const float* bl = (const float*)d_in[7];
    float* outp = (float*)d_out;

    dim3 gridBN(NN, BB);
    k0_init<<<64, 256>>>(Vd);
    k1_proj<<<gridBN, 384>>>(t, Qd, Kd, Qs, Ks);
    k2_sim<<<gridBN, 384>>>();
    k3_m<<<gridBN, 384>>>(al, bl);
    k5_heavy<<<gridBN, 256>>>(t, al, bl, outp);
}

// round 13
// speedup vs baseline: 1.0043x; 1.0043x over previous
#include <cuda_runtime.h>
#include <cuda_bf16.h>
#include <cstdint>

#define BB 2
#define NN 384
#define DD 256
#define DDIRC 128
#define DSIMC 64
#define EPSF 1e-6f
#define DELTAF 1e-6f

// ---------------- scratch (static device globals; no allocations) ----------------
__device__ float g_q [BB*NN*DSIMC];
__device__ float g_k [BB*NN*DSIMC];
__device__ float g_qd[BB*NN*DDIRC];
__device__ float g_kd[BB*NN*DDIRC];
__device__ float g_s [BB*NN*NN];
__device__ float g_m [BB*NN];
__device__ double g_stats[BB*2];
__device__ __nv_bfloat16 g_vdt[DD*DDIRC];   // Vdt[d][r] = Vd[r][d], bf16

// ---------------- K0: zero stats + transpose/convert Vd ----------------
__global__ void k0_init(const float* __restrict__ Vd) {
    int idx = blockIdx.x*blockDim.x + threadIdx.x;
    if (idx < BB*2) g_stats[idx] = 0.0;
    for (int i = idx; i < DD*DDIRC; i += gridDim.x*blockDim.x) {
        int d = i / DDIRC, r = i % DDIRC;
        g_vdt[i] = __float2bfloat16(Vd[r*DD + d]);
    }
}

// ---------------- K1: projections q,k,qd,kd ----------------
__global__ void k1_proj(const float* __restrict__ t,
                        const float* __restrict__ Qd, const float* __restrict__ Kd,
                        const float* __restrict__ Qs, const float* __restrict__ Ks) {
    int b = blockIdx.y, n = blockIdx.x;
    __shared__ float ts[DD];
    int tid = threadIdx.x;                  // 384 threads
    if (tid < DD) ts[tid] = t[(b*NN+n)*DD + tid];
    __syncthreads();
    const float* W; int ld, col; float* outp;
    if (tid < 64)       { W = Qs; ld = DSIMC; col = tid;     outp = &g_q [(b*NN+n)*DSIMC + col]; }
    else if (tid < 128) { W = Ks; ld = DSIMC; col = tid-64;  outp = &g_k [(b*NN+n)*DSIMC + col]; }
    else if (tid < 256) { W = Qd; ld = DDIRC; col = tid-128; outp = &g_qd[(b*NN+n)*DDIRC + col]; }
    else                { W = Kd; ld = DDIRC; col = tid-256; outp = &g_kd[(b*NN+n)*DDIRC + col]; }
    float acc = 0.f;
    #pragma unroll 8
    for (int r = 0; r < DD; r++) acc += ts[r] * W[r*ld + col];
    *outp = acc;
}

// ---------------- K2: symmetrized s + off-diagonal sum / sumsq ----------------
__global__ void k2_sim() {
    int b = blockIdx.y, i = blockIdx.x, j = threadIdx.x;   // 384 threads
    __shared__ float qi[DSIMC], ki[DSIMC];
    __shared__ float red0[12], red1[12];
    if (j < DSIMC)        qi[j]       = g_q[(b*NN+i)*DSIMC + j];
    else if (j < 2*DSIMC) ki[j-DSIMC] = g_k[(b*NN+i)*DSIMC + (j-DSIMC)];
    __syncthreads();
    const float4* kj = (const float4*)&g_k[(b*NN+j)*DSIMC];
    const float4* qj = (const float4*)&g_q[(b*NN+j)*DSIMC];
    float acc = 0.f;
    #pragma unroll
    for (int r4 = 0; r4 < DSIMC/4; r4++) {
        float4 kv = kj[r4], qv = qj[r4];
        acc += qi[4*r4+0]*kv.x + qi[4*r4+1]*kv.y + qi[4*r4+2]*kv.z + qi[4*r4+3]*kv.w;
        acc += ki[4*r4+0]*qv.x + ki[4*r4+1]*qv.y + ki[4*r4+2]*qv.z + ki[4*r4+3]*qv.w;
    }
    float s = acc * 0.0625f;   // 0.5 / sqrt(64)
    g_s[(b*NN+i)*NN + j] = s;
    float sv = (j == i) ? 0.f : s;
    float s2 = sv * sv;
    #pragma unroll
    for (int o = 16; o; o >>= 1) {
        sv += __shfl_xor_sync(~0u, sv, o);
        s2 += __shfl_xor_sync(~0u, s2, o);
    }
    int w = j >> 5, l = j & 31;
    if (!l) { red0[w] = sv; red1[w] = s2; }
    __syncthreads();
    if (j == 0) {
        double a = 0, c = 0;
        for (int w2 = 0; w2 < 12; w2++) { a += (double)red0[w2]; c += (double)red1[w2]; }
        atomicAdd(&g_stats[b*2+0], a);
        atomicAdd(&g_stats[b*2+1], c);
    }
}

// ---------------- K3: per-row exp-sum -> m ----------------
__global__ void k3_m(const float* __restrict__ al, const float* __restrict__ bl) {
    int b = blockIdx.y, i = blockIdx.x, j = threadIdx.x;   // 384 threads
    __shared__ float red[12];
    const float cnt = (float)(NN*(NN-1));
    float mu  = (float)(g_stats[b*2+0] / cnt);
    float var = (float)(g_stats[b*2+1] / cnt) - mu*mu;
    float inv = rsqrtf(var + EPSF);
    float a = al[0], bv = bl[0];
    float s  = g_s[(b*NN+i)*NN + j];
    float ts = a * ((s - mu) * inv) + bv;
    float e  = expf(ts);   // GAMMA = 1
    #pragma unroll
    for (int o = 16; o; o >>= 1) e += __shfl_xor_sync(~0u, e, o);
    int w = j >> 5, l = j & 31;
    if (!l) red[w] = e;
    __syncthreads();
    if (j == 0) {
        float E = 0.f;
        for (int w2 = 0; w2 < 12; w2++) E += red[w2];
        g_m[b*NN+i] = 1.f / (E + EPSF);
    }
}

// ---------------- K5: heavy fused gate + aggregation ----------------
__global__ void __launch_bounds__(256) k5_heavy(
    const float* __restrict__ t, const float* __restrict__ al,
    const float* __restrict__ bl, float* __restrict__ outp)
{
    const int b = blockIdx.y, i = blockIdx.x;
    const int tid  = threadIdx.x;
    const int lane = tid & 31, wid = tid >> 5;
    const int T = lane & 3, grp = lane >> 2;

    __shared__ float sm_ti[DD];
    __shared__ float sm_qdi[DDIRC], sm_kdi[DDIRC];
    __shared__ float sm_alpha[NN];
    __shared__ __align__(16) __nv_bfloat16 sm_U[16*136];
    __shared__ float sm_t[16*260];
    __shared__ float sm_red[8];

    // ---- prologue loads ----
    if (tid < DD) sm_ti[tid] = t[(b*NN+i)*DD + tid];
    if (tid < DDIRC)        sm_qdi[tid]        = g_qd[(b*NN+i)*DDIRC + tid];
    else if (tid < 2*DDIRC) sm_kdi[tid-DDIRC]  = g_kd[(b*NN+i)*DDIRC + tid - DDIRC];

    // ---- alpha row in smem ----
    const float cnt = (float)(NN*(NN-1));
    float mu  = (float)(g_stats[b*2+0] / cnt);
    float var = (float)(g_stats[b*2+1] / cnt) - mu*mu;
    float inv = rsqrtf(var + EPSF);
    float aa = al[0], bv = bl[0];
    float rs = 0.f;
    for (int j = tid; j < NN; j += 256) {
        float s  = g_s[(b*NN+i)*NN + j];
        float ts = aa * ((s - mu) * inv) + bv;
        float A  = 1.f / (1.f + expf(-ts));
        float w  = A * g_m[b*NN + j];
        sm_alpha[j] = A * w;
        rs += w;                                // rowsum of w includes diagonal
    }
    #pragma unroll
    for (int o = 16; o; o >>= 1) rs += __shfl_xor_sync(~0u, rs, o);
    if (!lane) sm_red[wid] = rs;
    __syncthreads();
    float rstot = 0.f;
    #pragma unroll
    for (int w2 = 0; w2 < 8; w2++) rstot += sm_red[w2];
    float rinv = 1.f / (rstot + DELTAF);
    for (int j = tid; j < NN; j += 256)
        sm_alpha[j] = (j == i) ? 0.f : sm_alpha[j] * rinv;

    // ---- preload B fragments (Vd) into registers: breg[kc][f][2] ----
    uint32_t breg[8][4][2];
    const int warpD = wid * 32;
    #pragma unroll
    for (int kc = 0; kc < 8; kc++)
        #pragma unroll
        for (int f = 0; f < 4; f++) {
            int n = warpD + 8*f + grp;
            const __nv_bfloat16* base = &g_vdt[n*DDIRC + kc*16 + 2*T];
            breg[kc][f][0] = *(const uint32_t*)(base);
            breg[kc][f][1] = *(const uint32_t*)(base + 8);
        }

    float acc[4][2] = {};

    const int jj = tid >> 4;           // 0..15 (row within tile)
    const int rb = (tid & 15) * 8;     // U-build r base
    const int db = (tid & 15) * 16;    // t-tile d base

    for (int jt = 0; jt < NN/16; jt++) {
        const int j0 = jt * 16;
        __syncthreads();
        // ---- build U tile (bf16) + t tile (f32) in smem ----
        {
            int j = j0 + jj;
            const float4* kdj = (const float4*)&g_kd[(b*NN+j)*DDIRC + rb];
            const float4* qdj = (const float4*)&g_qd[(b*NN+j)*DDIRC + rb];
            float4 kv0 = kdj[0], kv1 = kdj[1];
            float4 qv0 = qdj[0], qv1 = qdj[1];
            float kd_[8] = {kv0.x,kv0.y,kv0.z,kv0.w,kv1.x,kv1.y,kv1.z,kv1.w};
            float qd_[8] = {qv0.x,qv0.y,qv0.z,qv0.w,qv1.x,qv1.y,qv1.z,qv1.w};
            float u[8];
            #pragma unroll
            for (int v = 0; v < 8; v++)
                u[v] = sm_qdi[rb+v]*kd_[v] - qd_[v]*sm_kdi[rb+v];
            __nv_bfloat162* dst = (__nv_bfloat162*)&sm_U[jj*136 + rb];
            #pragma unroll
            for (int p = 0; p < 4; p++)
                dst[p] = __floats2bfloat162_rn(u[2*p], u[2*p+1]);

            const float4* tj = (const float4*)&t[(b*NN+j)*DD + db];
            float4 t0 = tj[0], t1 = tj[1], t2 = tj[2], t3 = tj[3];
            float* td = &sm_t[jj*260 + db];
            *(float4*)(td+0)  = t0;  *(float4*)(td+4)  = t1;
            *(float4*)(td+8)  = t2;  *(float4*)(td+12) = t3;
        }
        __syncthreads();

        // ---- MMA: Delta tile (16 j x 32 d per warp) ----
        float c[4][4] = {};
        #pragma unroll
        for (int kc = 0; kc < 8; kc++) {
            const __nv_bfloat16* u0 = &sm_U[grp*136     + kc*16 + 2*T];
            const __nv_bfloat16* u1 = &sm_U[(grp+8)*136 + kc*16 + 2*T];
            uint32_t a0 = *(const uint32_t*)(u0);
            uint32_t a1 = *(const uint32_t*)(u1);
            uint32_t a2 = *(const uint32_t*)(u0 + 8);
            uint32_t a3 = *(const uint32_t*)(u1 + 8);
            #pragma unroll
            for (int f = 0; f < 4; f++)
                asm volatile(
                    "mma.sync.aligned.m16n8k16.row.col.f32.bf16.bf16.f32 "
                    "{%0,%1,%2,%3}, {%4,%5,%6,%7}, {%8,%9}, {%0,%1,%2,%3};"
                    : "+f"(c[f][0]), "+f"(c[f][1]), "+f"(c[f][2]), "+f"(c[f][3])
                    : "r"(a0), "r"(a1), "r"(a2), "r"(a3),
                      "r"(breg[kc][f][0]), "r"(breg[kc][f][1]));
        }

        // ---- epilogue: sigmoid, alpha, (t_i - t_j), accumulate over j ----
        float ar0 = sm_alpha[j0 + grp];
        float ar1 = sm_alpha[j0 + grp + 8];
        #pragma unroll
        for (int f = 0; f < 4; f++) {
            int d0 = warpD + 8*f + 2*T;
            float ti0 = sm_ti[d0], ti1 = sm_ti[d0+1];
            float tj00 = sm_t[grp*260 + d0],       tj01 = sm_t[grp*260 + d0 + 1];
            float tj10 = sm_t[(grp+8)*260 + d0],   tj11 = sm_t[(grp+8)*260 + d0 + 1];
            float g00 = 1.f/(1.f + __expf(-c[f][0]));   // row grp,   col d0
            float g01 = 1.f/(1.f + __expf(-c[f][1]));   // row grp,   col d0+1
            float g10 = 1.f/(1.f + __expf(-c[f][2]));   // row grp+8, col d0
            float g11 = 1.f/(1.f + __expf(-c[f][3]));   // row grp+8, col d0+1
            acc[f][0] += ar0*g00*(ti0 - tj00) + ar1*g10*(ti0 - tj10);
            acc[f][1] += ar0*g01*(ti1 - tj01) + ar1*g11*(ti1 - tj11);
        }
    }

    // ---- reduce over the 8 row-groups (lanes differing in grp bits) ----
    #pragma unroll
    for (int f = 0; f < 4; f++)
        #pragma unroll
        for (int e = 0; e < 2; e++) {
            float v = acc[f][e];
            v += __shfl_xor_sync(~0u, v, 4);
            v += __shfl_xor_sync(~0u, v, 8);
            v += __shfl_xor_sync(~0u, v, 16);
            acc[f][e] = v;
        }
    if (grp == 0) {
        #pragma unroll
        for (int f = 0; f < 4; f++) {
            int d0 = warpD + 8*f + 2*T;
            outp[(b*NN+i)*DD + d0]   = sm_ti[d0]   - acc[f][0];
            outp[(b*NN+i)*DD + d0+1] = sm_ti[d0+1] - acc[f][1];
        }
    }
}

// ---------------- launch ----------------
extern "C" void kernel_launch(void* const* d_in, const int* in_sizes, int n_in,
                              void* d_out, int out_size) {
    const float* t  = (const float*)d_in[0];
    const float* Qd = (const float*)d_in[1];
    const float* Kd = (const float*)d_in[2];
    const float* Vd = (const float*)d_in[3];
    const float* Qs = (const float*)d_in[4];
    const float* Ks = (const float*)d_in[5];
    const float* al = (const float*)d_in[6];
    const float* bl = (const float*)d_in[7];
    float* outp = (float*)d_out;

    dim3 gridBN(NN, BB);
    k0_init<<<64, 256>>>(Vd);
    k1_proj<<<gridBN, 384>>>(t, Qd, Kd, Qs, Ks);
    k2_sim<<<gridBN, 384>>>();
    k3_m<<<gridBN, 384>>>(al, bl);
    k5_heavy<<<gridBN, 256>>>(t, al, bl, outp);
}

// round 14
// speedup vs baseline: 1.8707x; 1.8628x over previous
#include <cuda_runtime.h>
#include <cuda_bf16.h>
#include <cstdint>

#define BB 2
#define NN 384
#define DD 256
#define DDIRC 128
#define DSIMC 64
#define EPSF 1e-6f
#define DELTAF 1e-6f

// ---------------- scratch (static device globals; no allocations) ----------------
__device__ float g_q [BB*NN*DSIMC];
__device__ float g_k [BB*NN*DSIMC];
__device__ float g_qd[BB*NN*DDIRC];
__device__ float g_kd[BB*NN*DDIRC];
__device__ float g_s [BB*NN*NN];
__device__ float g_m [BB*NN];
__device__ double g_stats[BB*2];
__device__ __nv_bfloat16 g_vdt[DD*DDIRC];   // Vdt[d][r] = Vd[r][d], bf16

__device__ __forceinline__ uint32_t smem_u32(const void* p) {
    return (uint32_t)__cvta_generic_to_shared(p);
}
__device__ __forceinline__ void cp16(uint32_t dst, const float* src) {
    asm volatile("cp.async.cg.shared.global [%0], [%1], 16;\n" :: "r"(dst), "l"(src));
}

// ---------------- K1: projections (8 rows/block) + merged init ----------------
__global__ void k1_proj(const float* __restrict__ t,
                        const float* __restrict__ Qd, const float* __restrict__ Kd,
                        const float* __restrict__ Qs, const float* __restrict__ Ks,
                        const float* __restrict__ Vd) {
    const int b = blockIdx.y, n0 = blockIdx.x * 8;
    const int tid = threadIdx.x;                 // 384 threads

    if (b == 0) {
        for (int i = blockIdx.x * 384 + tid; i < DD*DDIRC; i += 48*384) {
            int d = i / DDIRC, r = i % DDIRC;
            g_vdt[i] = __float2bfloat16(Vd[r*DD + d]);
        }
        if (blockIdx.x == 0 && tid < BB*2) g_stats[tid] = 0.0;
    }

    __shared__ float ts[8*DD];
    for (int idx = tid; idx < 8*DD; idx += 384)
        ts[idx] = t[(b*NN + n0 + (idx >> 8))*DD + (idx & 255)];
    __syncthreads();

    const float* W; int ld, col; float* outp; int ostride;
    if (tid < 64)       { W = Qs; ld = DSIMC; col = tid;     outp = &g_q [(b*NN+n0)*DSIMC + col]; ostride = DSIMC; }
    else if (tid < 128) { W = Ks; ld = DSIMC; col = tid-64;  outp = &g_k [(b*NN+n0)*DSIMC + col]; ostride = DSIMC; }
    else if (tid < 256) { W = Qd; ld = DDIRC; col = tid-128; outp = &g_qd[(b*NN+n0)*DDIRC + col]; ostride = DDIRC; }
    else                { W = Kd; ld = DDIRC; col = tid-256; outp = &g_kd[(b*NN+n0)*DDIRC + col]; ostride = DDIRC; }

    float acc[8] = {};
    #pragma unroll 4
    for (int r = 0; r < DD; r++) {
        float w = W[r*ld + col];
        #pragma unroll
        for (int m = 0; m < 8; m++) acc[m] += ts[m*DD + r] * w;
    }
    #pragma unroll
    for (int m = 0; m < 8; m++) outp[m*ostride] = acc[m];
}

// ---------------- K2: symmetrized s + off-diagonal stats (8 rows/block) ----------------
__global__ void k2_sim() {
    const int b = blockIdx.y, i0 = blockIdx.x * 8, j = threadIdx.x;   // 384 threads
    __shared__ float4 qi[8][16], ki[8][16];
    __shared__ float red0[12], red1[12];
    for (int idx = j; idx < 128; idx += 384) {
        int m = idx >> 4, r4 = idx & 15;
        qi[m][r4] = ((const float4*)&g_q[(b*NN + i0 + m)*DSIMC])[r4];
        ki[m][r4] = ((const float4*)&g_k[(b*NN + i0 + m)*DSIMC])[r4];
    }
    __syncthreads();

    const float4* kj = (const float4*)&g_k[(b*NN+j)*DSIMC];
    const float4* qj = (const float4*)&g_q[(b*NN+j)*DSIMC];
    float acc[8] = {};
    #pragma unroll
    for (int r4 = 0; r4 < 16; r4++) {
        float4 kv = kj[r4], qv = qj[r4];
        #pragma unroll
        for (int m = 0; m < 8; m++) {
            float4 q4 = qi[m][r4], k4 = ki[m][r4];
            acc[m] += q4.x*kv.x + q4.y*kv.y + q4.z*kv.z + q4.w*kv.w
                    + k4.x*qv.x + k4.y*qv.y + k4.z*qv.z + k4.w*qv.w;
        }
    }
    float sv = 0.f, s2 = 0.f;
    #pragma unroll
    for (int m = 0; m < 8; m++) {
        float s = acc[m] * 0.0625f;   // 0.5 / sqrt(64)
        g_s[(b*NN + i0 + m)*NN + j] = s;
        float v = (j == i0 + m) ? 0.f : s;
        sv += v; s2 += v*v;
    }
    #pragma unroll
    for (int o = 16; o; o >>= 1) {
        sv += __shfl_xor_sync(~0u, sv, o);
        s2 += __shfl_xor_sync(~0u, s2, o);
    }
    int w = j >> 5, l = j & 31;
    if (!l) { red0[w] = sv; red1[w] = s2; }
    __syncthreads();
    if (j == 0) {
        double a = 0, c = 0;
        for (int w2 = 0; w2 < 12; w2++) { a += (double)red0[w2]; c += (double)red1[w2]; }
        atomicAdd(&g_stats[b*2+0], a);
        atomicAdd(&g_stats[b*2+1], c);
    }
}

// ---------------- K3: per-row exp-sum -> m (8 rows/block) ----------------
__global__ void k3_m(const float* __restrict__ al, const float* __restrict__ bl) {
    const int b = blockIdx.y, i0 = blockIdx.x * 8, j = threadIdx.x;   // 384 threads
    __shared__ float red[12][8];
    const float cnt = (float)(NN*(NN-1));
    float mu  = (float)(g_stats[b*2+0] / cnt);
    float var = (float)(g_stats[b*2+1] / cnt) - mu*mu;
    float inv = rsqrtf(var + EPSF);
    float a = al[0], bv = bl[0];
    float e[8];
    #pragma unroll
    for (int m = 0; m < 8; m++) {
        float s = g_s[(b*NN + i0 + m)*NN + j];
        e[m] = __expf(a * ((s - mu) * inv) + bv);   // GAMMA = 1
    }
    #pragma unroll
    for (int m = 0; m < 8; m++)
        #pragma unroll
        for (int o = 16; o; o >>= 1) e[m] += __shfl_xor_sync(~0u, e[m], o);
    int w = j >> 5, l = j & 31;
    if (!l) {
        #pragma unroll
        for (int m = 0; m < 8; m++) red[w][m] = e[m];
    }
    __syncthreads();
    if (j < 8) {
        float E = 0.f;
        for (int w2 = 0; w2 < 12; w2++) E += red[w2][j];
        g_m[b*NN + i0 + j] = 1.f / (E + EPSF);
    }
}

// ---------------- K5: heavy fused gate + aggregation (pipelined) ----------------
__global__ void __launch_bounds__(256, 2) k5_heavy(
    const float* __restrict__ t, const float* __restrict__ al,
    const float* __restrict__ bl, float* __restrict__ outp)
{
    const int b = blockIdx.y, i = blockIdx.x;
    const int tid  = threadIdx.x;
    const int lane = tid & 31, wid = tid >> 5;
    const int T = lane & 3, grp = lane >> 2;

    __shared__ float sm_ti[DD];
    __shared__ float sm_qdi[DDIRC], sm_kdi[DDIRC];
    __shared__ float sm_alpha[NN];
    __shared__ __align__(16) __nv_bfloat16 sm_U[2][16*136];
    __shared__ __align__(16) float sm_t[2][16*260];
    __shared__ float sm_red[8];

    // ---- prologue loads ----
    if (tid < DD) sm_ti[tid] = t[(b*NN+i)*DD + tid];
    if (tid < DDIRC)        sm_qdi[tid]        = g_qd[(b*NN+i)*DDIRC + tid];
    else if (tid < 2*DDIRC) sm_kdi[tid-DDIRC]  = g_kd[(b*NN+i)*DDIRC + tid - DDIRC];

    // ---- alpha row in smem ----
    const float cnt = (float)(NN*(NN-1));
    float mu  = (float)(g_stats[b*2+0] / cnt);
    float var = (float)(g_stats[b*2+1] / cnt) - mu*mu;
    float inv = rsqrtf(var + EPSF);
    float aa = al[0], bv = bl[0];
    float rs = 0.f;
    for (int j = tid; j < NN; j += 256) {
        float s  = g_s[(b*NN+i)*NN + j];
        float ts = aa * ((s - mu) * inv) + bv;
        float A  = 1.f / (1.f + __expf(-ts));
        float w  = A * g_m[b*NN + j];
        sm_alpha[j] = A * w;
        rs += w;                                // rowsum of w includes diagonal
    }
    #pragma unroll
    for (int o = 16; o; o >>= 1) rs += __shfl_xor_sync(~0u, rs, o);
    if (!lane) sm_red[wid] = rs;
    __syncthreads();                            // also covers sm_qdi/sm_kdi
    float rstot = 0.f;
    #pragma unroll
    for (int w2 = 0; w2 < 8; w2++) rstot += sm_red[w2];
    float rinv = 1.f / (rstot + DELTAF);
    for (int j = tid; j < NN; j += 256)
        sm_alpha[j] = (j == i) ? 0.f : sm_alpha[j] * rinv;

    // ---- preload B fragments (Vd) into registers ----
    uint32_t breg[8][4][2];
    const int warpD = wid * 32;
    #pragma unroll
    for (int kc = 0; kc < 8; kc++)
        #pragma unroll
        for (int f = 0; f < 4; f++) {
            int n = warpD + 8*f + grp;
            const __nv_bfloat16* base = &g_vdt[n*DDIRC + kc*16 + 2*T];
            breg[kc][f][0] = *(const uint32_t*)(base);
            breg[kc][f][1] = *(const uint32_t*)(base + 8);
        }

    const int jj = tid >> 4;           // 0..15 (row within tile)
    const int rb = (tid & 15) * 8;     // U-build r base
    const int c0 = (tid & 15);         // cp.async chunk id

    float4 kv0, kv1, qv0, qv1;

    // ---- pipeline prologue: tile 0 ----
    {
        const float* src = &t[(b*NN + jj)*DD + c0*4];
        uint32_t dst = smem_u32(&sm_t[0][jj*260 + c0*4]);
        #pragma unroll
        for (int c = 0; c < 4; c++) cp16(dst + c*256, src + c*64);
        asm volatile("cp.async.commit_group;\n");

        const float4* kp = (const float4*)&g_kd[(b*NN + jj)*DDIRC + rb];
        const float4* qp = (const float4*)&g_qd[(b*NN + jj)*DDIRC + rb];
        kv0 = kp[0]; kv1 = kp[1]; qv0 = qp[0]; qv1 = qp[1];

        // build U tile 0
        float kd_[8] = {kv0.x,kv0.y,kv0.z,kv0.w,kv1.x,kv1.y,kv1.z,kv1.w};
        float qd_[8] = {qv0.x,qv0.y,qv0.z,qv0.w,qv1.x,qv1.y,qv1.z,qv1.w};
        __nv_bfloat162* ud = (__nv_bfloat162*)&sm_U[0][jj*136 + rb];
        #pragma unroll
        for (int p = 0; p < 4; p++) {
            float u0 = sm_qdi[rb+2*p  ]*kd_[2*p  ] - qd_[2*p  ]*sm_kdi[rb+2*p  ];
            float u1 = sm_qdi[rb+2*p+1]*kd_[2*p+1] - qd_[2*p+1]*sm_kdi[rb+2*p+1];
            ud[p] = __floats2bfloat162_rn(u0, u1);
        }
        asm volatile("cp.async.wait_group 0;\n");
    }
    __syncthreads();   // covers alpha normalize + U[0] + t[0]

    float acc[4][2] = {};

    for (int jt = 0; jt < NN/16; jt++) {
        const int cur = jt & 1, nxt = cur ^ 1;
        const int j0 = jt * 16;
        const bool more = (jt + 1 < NN/16);

        // ---- prefetch next tile (t via cp.async, kd/qd into regs) ----
        if (more) {
            const float* src = &t[(b*NN + j0 + 16 + jj)*DD + c0*4];
            uint32_t dst = smem_u32(&sm_t[nxt][jj*260 + c0*4]);
            #pragma unroll
            for (int c = 0; c < 4; c++) cp16(dst + c*256, src + c*64);
            asm volatile("cp.async.commit_group;\n");
            const float4* kp = (const float4*)&g_kd[(b*NN + j0 + 16 + jj)*DDIRC + rb];
            const float4* qp = (const float4*)&g_qd[(b*NN + j0 + 16 + jj)*DDIRC + rb];
            kv0 = kp[0]; kv1 = kp[1]; qv0 = qp[0]; qv1 = qp[1];
        }

        // ---- MMA on current U buffer (overlaps prefetch latency) ----
        float cf[4][4] = {};
        #pragma unroll
        for (int kc = 0; kc < 8; kc++) {
            const __nv_bfloat16* u0 = &sm_U[cur][grp*136     + kc*16 + 2*T];
            const __nv_bfloat16* u1 = &sm_U[cur][(grp+8)*136 + kc*16 + 2*T];
            uint32_t a0 = *(const uint32_t*)(u0);
            uint32_t a1 = *(const uint32_t*)(u1);
            uint32_t a2 = *(const uint32_t*)(u0 + 8);
            uint32_t a3 = *(const uint32_t*)(u1 + 8);
            #pragma unroll
            for (int f = 0; f < 4; f++)
                asm volatile(
                    "mma.sync.aligned.m16n8k16.row.col.f32.bf16.bf16.f32 "
                    "{%0,%1,%2,%3}, {%4,%5,%6,%7}, {%8,%9}, {%0,%1,%2,%3};"
                    : "+f"(cf[f][0]), "+f"(cf[f][1]), "+f"(cf[f][2]), "+f"(cf[f][3])
                    : "r"(a0), "r"(a1), "r"(a2), "r"(a3),
                      "r"(breg[kc][f][0]), "r"(breg[kc][f][1]));
        }

        // ---- build next U tile from prefetched regs ----
        if (more) {
            float kd_[8] = {kv0.x,kv0.y,kv0.z,kv0.w,kv1.x,kv1.y,kv1.z,kv1.w};
            float qd_[8] = {qv0.x,qv0.y,qv0.z,qv0.w,qv1.x,qv1.y,qv1.z,qv1.w};
            __nv_bfloat162* ud = (__nv_bfloat162*)&sm_U[nxt][jj*136 + rb];
            #pragma unroll
            for (int p = 0; p < 4; p++) {
                float u0 = sm_qdi[rb+2*p  ]*kd_[2*p  ] - qd_[2*p  ]*sm_kdi[rb+2*p  ];
                float u1 = sm_qdi[rb+2*p+1]*kd_[2*p+1] - qd_[2*p+1]*sm_kdi[rb+2*p+1];
                ud[p] = __floats2bfloat162_rn(u0, u1);
            }
        }

        // ---- epilogue: sigmoid, alpha, (t_i - t_j), accumulate over j ----
        float ar0 = sm_alpha[j0 + grp];
        float ar1 = sm_alpha[j0 + grp + 8];
        #pragma unroll
        for (int f = 0; f < 4; f++) {
            int d0 = warpD + 8*f + 2*T;
            float ti0 = sm_ti[d0], ti1 = sm_ti[d0+1];
            float tj00 = sm_t[cur][grp*260 + d0],     tj01 = sm_t[cur][grp*260 + d0 + 1];
            float tj10 = sm_t[cur][(grp+8)*260 + d0], tj11 = sm_t[cur][(grp+8)*260 + d0 + 1];
            float g00 = 1.f/(1.f + __expf(-cf[f][0]));
            float g01 = 1.f/(1.f + __expf(-cf[f][1]));
            float g10 = 1.f/(1.f + __expf(-cf[f][2]));
            float g11 = 1.f/(1.f + __expf(-cf[f][3]));
            acc[f][0] += ar0*g00*(ti0 - tj00) + ar1*g10*(ti0 - tj10);
            acc[f][1] += ar0*g01*(ti1 - tj01) + ar1*g11*(ti1 - tj11);
        }

        asm volatile("cp.async.wait_group 0;\n");
        __syncthreads();
    }

    // ---- reduce over the 8 row-groups ----
    #pragma unroll
    for (int f = 0; f < 4; f++)
        #pragma unroll
        for (int e = 0; e < 2; e++) {
            float v = acc[f][e];
            v += __shfl_xor_sync(~0u, v, 4);
            v += __shfl_xor_sync(~0u, v, 8);
            v += __shfl_xor_sync(~0u, v, 16);
            acc[f][e] = v;
        }
    if (grp == 0) {
        #pragma unroll
        for (int f = 0; f < 4; f++) {
            int d0 = warpD + 8*f + 2*T;
            outp[(b*NN+i)*DD + d0]   = sm_ti[d0]   - acc[f][0];
            outp[(b*NN+i)*DD + d0+1] = sm_ti[d0+1] - acc[f][1];
        }
    }
}

// ---------------- launch ----------------
extern "C" void kernel_launch(void* const* d_in, const int* in_sizes, int n_in,
                              void* d_out, int out_size) {
    const float* t  = (const float*)d_in[0];
    const float* Qd = (const float*)d_in[1];
    const float* Kd = (const float*)d_in[2];
    const float* Vd = (const float*)d_in[3];
    const float* Qs = (const float*)d_in[4];
    const float* Ks = (const float*)d_in[5];
    const float* al = (const float*)d_in[6];
    const float* bl = (const float*)d_in[7];
    float* outp = (float*)d_out;

    dim3 grid48(NN/8, BB);
    dim3 gridBN(NN, BB);
    k1_proj<<<grid48, 384>>>(t, Qd, Kd, Qs, Ks, Vd);
    k2_sim<<<grid48, 384>>>();
    k3_m<<<grid48, 384>>>(al, bl);
    k5_heavy<<<gridBN, 256>>>(t, al, bl, outp);
}

// round 15
// speedup vs baseline: 1.8724x; 1.0009x over previous
#include <cuda_runtime.h>
#include <cuda_bf16.h>
#include <cstdint>

#define BB 2
#define NN 384
#define DD 256
#define DDIRC 128
#define DSIMC 64
#define EPSF 1e-6f
#define DELTAF 1e-6f

// ---------------- scratch (static device globals; no allocations) ----------------
__device__ float g_q [BB*NN*DSIMC];
__device__ float g_k [BB*NN*DSIMC];
__device__ float g_qd[BB*NN*DDIRC];
__device__ float g_kd[BB*NN*DDIRC];
__device__ float g_s [BB*NN*NN];
__device__ float g_m [BB*NN];
__device__ double g_stats[BB*2];
__device__ __nv_bfloat16 g_vdt[DD*DDIRC];   // Vdt[d][r] = Vd[r][d], bf16

__device__ __forceinline__ uint32_t smem_u32(const void* p) {
    return (uint32_t)__cvta_generic_to_shared(p);
}
__device__ __forceinline__ void cp16(uint32_t dst, const float* src) {
    asm volatile("cp.async.cg.shared.global [%0], [%1], 16;\n" :: "r"(dst), "l"(src));
}

// ---------------- K1: projections (8 rows/block) + merged init ----------------
__global__ void k1_proj(const float* __restrict__ t,
                        const float* __restrict__ Qd, const float* __restrict__ Kd,
                        const float* __restrict__ Qs, const float* __restrict__ Ks,
                        const float* __restrict__ Vd) {
    const int b = blockIdx.y, n0 = blockIdx.x * 8;
    const int tid = threadIdx.x;                 // 384 threads

    if (b == 0) {
        for (int i = blockIdx.x * 384 + tid; i < DD*DDIRC; i += 48*384) {
            int d = i / DDIRC, r = i % DDIRC;
            g_vdt[i] = __float2bfloat16(Vd[r*DD + d]);
        }
        if (blockIdx.x == 0 && tid < BB*2) g_stats[tid] = 0.0;
    }

    __shared__ float ts[8*DD];
    for (int idx = tid; idx < 8*DD; idx += 384)
        ts[idx] = t[(b*NN + n0 + (idx >> 8))*DD + (idx & 255)];
    __syncthreads();

    const float* W; int ld, col; float* outp; int ostride;
    if (tid < 64)       { W = Qs; ld = DSIMC; col = tid;     outp = &g_q [(b*NN+n0)*DSIMC + col]; ostride = DSIMC; }
    else if (tid < 128) { W = Ks; ld = DSIMC; col = tid-64;  outp = &g_k [(b*NN+n0)*DSIMC + col]; ostride = DSIMC; }
    else if (tid < 256) { W = Qd; ld = DDIRC; col = tid-128; outp = &g_qd[(b*NN+n0)*DDIRC + col]; ostride = DDIRC; }
    else                { W = Kd; ld = DDIRC; col = tid-256; outp = &g_kd[(b*NN+n0)*DDIRC + col]; ostride = DDIRC; }

    float acc[8] = {};
    #pragma unroll 4
    for (int r = 0; r < DD; r++) {
        float w = W[r*ld + col];
        #pragma unroll
        for (int m = 0; m < 8; m++) acc[m] += ts[m*DD + r] * w;
    }
    #pragma unroll
    for (int m = 0; m < 8; m++) outp[m*ostride] = acc[m];
}

// ---------------- K2: symmetrized s + off-diagonal stats (8 rows/block) ----------------
__global__ void k2_sim() {
    const int b = blockIdx.y, i0 = blockIdx.x * 8, j = threadIdx.x;   // 384 threads
    __shared__ float4 qi[8][16], ki[8][16];
    __shared__ float red0[12], red1[12];
    for (int idx = j; idx < 128; idx += 384) {
        int m = idx >> 4, r4 = idx & 15;
        qi[m][r4] = ((const float4*)&g_q[(b*NN + i0 + m)*DSIMC])[r4];
        ki[m][r4] = ((const float4*)&g_k[(b*NN + i0 + m)*DSIMC])[r4];
    }
    __syncthreads();

    const float4* kj = (const float4*)&g_k[(b*NN+j)*DSIMC];
    const float4* qj = (const float4*)&g_q[(b*NN+j)*DSIMC];
    float acc[8] = {};
    #pragma unroll
    for (int r4 = 0; r4 < 16; r4++) {
        float4 kv = kj[r4], qv = qj[r4];
        #pragma unroll
        for (int m = 0; m < 8; m++) {
            float4 q4 = qi[m][r4], k4 = ki[m][r4];
            acc[m] += q4.x*kv.x + q4.y*kv.y + q4.z*kv.z + q4.w*kv.w
                    + k4.x*qv.x + k4.y*qv.y + k4.z*qv.z + k4.w*qv.w;
        }
    }
    float sv = 0.f, s2 = 0.f;
    #pragma unroll
    for (int m = 0; m < 8; m++) {
        float s = acc[m] * 0.0625f;   // 0.5 / sqrt(64)
        g_s[(b*NN + i0 + m)*NN + j] = s;
        float v = (j == i0 + m) ? 0.f : s;
        sv += v; s2 += v*v;
    }
    #pragma unroll
    for (int o = 16; o; o >>= 1) {
        sv += __shfl_xor_sync(~0u, sv, o);
        s2 += __shfl_xor_sync(~0u, s2, o);
    }
    int w = j >> 5, l = j & 31;
    if (!l) { red0[w] = sv; red1[w] = s2; }
    __syncthreads();
    if (j == 0) {
        double a = 0, c = 0;
        for (int w2 = 0; w2 < 12; w2++) { a += (double)red0[w2]; c += (double)red1[w2]; }
        atomicAdd(&g_stats[b*2+0], a);
        atomicAdd(&g_stats[b*2+1], c);
    }
}

// ---------------- K3: per-row exp-sum -> m (8 rows/block) ----------------
__global__ void k3_m(const float* __restrict__ al, const float* __restrict__ bl) {
    const int b = blockIdx.y, i0 = blockIdx.x * 8, j = threadIdx.x;   // 384 threads
    __shared__ float red[12][8];
    const float cnt = (float)(NN*(NN-1));
    float mu  = (float)(g_stats[b*2+0] / cnt);
    float var = (float)(g_stats[b*2+1] / cnt) - mu*mu;
    float inv = rsqrtf(var + EPSF);
    float a = al[0], bv = bl[0];
    float e[8];
    #pragma unroll
    for (int m = 0; m < 8; m++) {
        float s = g_s[(b*NN + i0 + m)*NN + j];
        e[m] = __expf(a * ((s - mu) * inv) + bv);   // GAMMA = 1
    }
    #pragma unroll
    for (int m = 0; m < 8; m++)
        #pragma unroll
        for (int o = 16; o; o >>= 1) e[m] += __shfl_xor_sync(~0u, e[m], o);
    int w = j >> 5, l = j & 31;
    if (!l) {
        #pragma unroll
        for (int m = 0; m < 8; m++) red[w][m] = e[m];
    }
    __syncthreads();
    if (j < 8) {
        float E = 0.f;
        for (int w2 = 0; w2 < 12; w2++) E += red[w2][j];
        g_m[b*NN + i0 + j] = 1.f / (E + EPSF);
    }
}

// ---------------- K5: heavy fused gate + aggregation (pipelined) ----------------
__global__ void __launch_bounds__(256, 2) k5_heavy(
    const float* __restrict__ t, const float* __restrict__ al,
    const float* __restrict__ bl, float* __restrict__ outp)
{
    const int b = blockIdx.y, i = blockIdx.x;
    const int tid  = threadIdx.x;
    const int lane = tid & 31, wid = tid >> 5;
    const int T = lane & 3, grp = lane >> 2;

    __shared__ float sm_ti[DD];
    __shared__ float sm_qdi[DDIRC], sm_kdi[DDIRC];
    __shared__ float sm_alpha[NN];
    __shared__ __align__(16) __nv_bfloat16 sm_U[2][16*136];
    __shared__ __align__(16) float sm_t[2][16*260];
    __shared__ float sm_red[8];

    // ---- prologue loads ----
    if (tid < DD) sm_ti[tid] = t[(b*NN+i)*DD + tid];
    if (tid < DDIRC)        sm_qdi[tid]        = g_qd[(b*NN+i)*DDIRC + tid];
    else if (tid < 2*DDIRC) sm_kdi[tid-DDIRC]  = g_kd[(b*NN+i)*DDIRC + tid - DDIRC];

    // ---- alpha row in smem ----
    const float cnt = (float)(NN*(NN-1));
    float mu  = (float)(g_stats[b*2+0] / cnt);
    float var = (float)(g_stats[b*2+1] / cnt) - mu*mu;
    float inv = rsqrtf(var + EPSF);
    float aa = al[0], bv = bl[0];
    float rs = 0.f;
    for (int j = tid; j < NN; j += 256) {
        float s  = g_s[(b*NN+i)*NN + j];
        float ts = aa * ((s - mu) * inv) + bv;
        float A  = 1.f / (1.f + __expf(-ts));
        float w  = A * g_m[b*NN + j];
        sm_alpha[j] = A * w;
        rs += w;                                // rowsum of w includes diagonal
    }
    #pragma unroll
    for (int o = 16; o; o >>= 1) rs += __shfl_xor_sync(~0u, rs, o);
    if (!lane) sm_red[wid] = rs;
    __syncthreads();                            // also covers sm_qdi/sm_kdi
    float rstot = 0.f;
    #pragma unroll
    for (int w2 = 0; w2 < 8; w2++) rstot += sm_red[w2];
    float rinv = 1.f / (rstot + DELTAF);
    for (int j = tid; j < NN; j += 256)
        sm_alpha[j] = (j == i) ? 0.f : sm_alpha[j] * rinv;

    // ---- preload B fragments (Vd) into registers ----
    uint32_t breg[8][4][2];
    const int warpD = wid * 32;
    #pragma unroll
    for (int kc = 0; kc < 8; kc++)
        #pragma unroll
        for (int f = 0; f < 4; f++) {
            int n = warpD + 8*f + grp;
            const __nv_bfloat16* base = &g_vdt[n*DDIRC + kc*16 + 2*T];
            breg[kc][f][0] = *(const uint32_t*)(base);
            breg[kc][f][1] = *(const uint32_t*)(base + 8);
        }

    const int jj = tid >> 4;           // 0..15 (row within tile)
    const int rb = (tid & 15) * 8;     // U-build r base
    const int c0 = (tid & 15);         // cp.async chunk id

    float4 kv0, kv1, qv0, qv1;

    // ---- pipeline prologue: tile 0 ----
    {
        const float* src = &t[(b*NN + jj)*DD + c0*4];
        uint32_t dst = smem_u32(&sm_t[0][jj*260 + c0*4]);
        #pragma unroll
        for (int c = 0; c < 4; c++) cp16(dst + c*256, src + c*64);
        asm volatile("cp.async.commit_group;\n");

        const float4* kp = (const float4*)&g_kd[(b*NN + jj)*DDIRC + rb];
        const float4* qp = (const float4*)&g_qd[(b*NN + jj)*DDIRC + rb];
        kv0 = kp[0]; kv1 = kp[1]; qv0 = qp[0]; qv1 = qp[1];

        // build U tile 0
        float kd_[8] = {kv0.x,kv0.y,kv0.z,kv0.w,kv1.x,kv1.y,kv1.z,kv1.w};
        float qd_[8] = {qv0.x,qv0.y,qv0.z,qv0.w,qv1.x,qv1.y,qv1.z,qv1.w};
        __nv_bfloat162* ud = (__nv_bfloat162*)&sm_U[0][jj*136 + rb];
        #pragma unroll
        for (int p = 0; p < 4; p++) {
            float u0 = sm_qdi[rb+2*p  ]*kd_[2*p  ] - qd_[2*p  ]*sm_kdi[rb+2*p  ];
            float u1 = sm_qdi[rb+2*p+1]*kd_[2*p+1] - qd_[2*p+1]*sm_kdi[rb+2*p+1];
            ud[p] = __floats2bfloat162_rn(u0, u1);
        }
        asm volatile("cp.async.wait_group 0;\n");
    }
    __syncthreads();   // covers alpha normalize + U[0] + t[0]

    float acc[4][2] = {};

    for (int jt = 0; jt < NN/16; jt++) {
        const int cur = jt & 1, nxt = cur ^ 1;
        const int j0 = jt * 16;
        const bool more = (jt + 1 < NN/16);

        // ---- prefetch next tile (t via cp.async, kd/qd into regs) ----
        if (more) {
            const float* src = &t[(b*NN + j0 + 16 + jj)*DD + c0*4];
            uint32_t dst = smem_u32(&sm_t[nxt][jj*260 + c0*4]);
            #pragma unroll
            for (int c = 0; c < 4; c++) cp16(dst + c*256, src + c*64);
            asm volatile("cp.async.commit_group;\n");
            const float4* kp = (const float4*)&g_kd[(b*NN + j0 + 16 + jj)*DDIRC + rb];
            const float4* qp = (const float4*)&g_qd[(b*NN + j0 + 16 + jj)*DDIRC + rb];
            kv0 = kp[0]; kv1 = kp[1]; qv0 = qp[0]; qv1 = qp[1];
        }

        // ---- MMA on current U buffer (overlaps prefetch latency) ----
        float cf[4][4] = {};
        #pragma unroll
        for (int kc = 0; kc < 8; kc++) {
            const __nv_bfloat16* u0 = &sm_U[cur][grp*136     + kc*16 + 2*T];
            const __nv_bfloat16* u1 = &sm_U[cur][(grp+8)*136 + kc*16 + 2*T];
            uint32_t a0 = *(const uint32_t*)(u0);
            uint32_t a1 = *(const uint32_t*)(u1);
            uint32_t a2 = *(const uint32_t*)(u0 + 8);
            uint32_t a3 = *(const uint32_t*)(u1 + 8);
            #pragma unroll
            for (int f = 0; f < 4; f++)
                asm volatile(
                    "mma.sync.aligned.m16n8k16.row.col.f32.bf16.bf16.f32 "
                    "{%0,%1,%2,%3}, {%4,%5,%6,%7}, {%8,%9}, {%0,%1,%2,%3};"
                    : "+f"(cf[f][0]), "+f"(cf[f][1]), "+f"(cf[f][2]), "+f"(cf[f][3])
                    : "r"(a0), "r"(a1), "r"(a2), "r"(a3),
                      "r"(breg[kc][f][0]), "r"(breg[kc][f][1]));
        }

        // ---- build next U tile from prefetched regs ----
        if (more) {
            float kd_[8] = {kv0.x,kv0.y,kv0.z,kv0.w,kv1.x,kv1.y,kv1.z,kv1.w};
            float qd_[8] = {qv0.x,qv0.y,qv0.z,qv0.w,qv1.x,qv1.y,qv1.z,qv1.w};
            __nv_bfloat162* ud = (__nv_bfloat162*)&sm_U[nxt][jj*136 + rb];
            #pragma unroll
            for (int p = 0; p < 4; p++) {
                float u0 = sm_qdi[rb+2*p  ]*kd_[2*p  ] - qd_[2*p  ]*sm_kdi[rb+2*p  ];
                float u1 = sm_qdi[rb+2*p+1]*kd_[2*p+1] - qd_[2*p+1]*sm_kdi[rb+2*p+1];
                ud[p] = __floats2bfloat162_rn(u0, u1);
            }
        }

        // ---- epilogue: sigmoid, alpha, (t_i - t_j), accumulate over j ----
        float ar0 = sm_alpha[j0 + grp];
        float ar1 = sm_alpha[j0 + grp + 8];
        #pragma unroll
        for (int f = 0; f < 4; f++) {
            int d0 = warpD + 8*f + 2*T;
            float ti0 = sm_ti[d0], ti1 = sm_ti[d0+1];
            float tj00 = sm_t[cur][grp*260 + d0],     tj01 = sm_t[cur][grp*260 + d0 + 1];
            float tj10 = sm_t[cur][(grp+8)*260 + d0], tj11 = sm_t[cur][(grp+8)*260 + d0 + 1];
            float g00 = 1.f/(1.f + __expf(-cf[f][0]));
            float g01 = 1.f/(1.f + __expf(-cf[f][1]));
            float g10 = 1.f/(1.f + __expf(-cf[f][2]));
            float g11 = 1.f/(1.f + __expf(-cf[f][3]));
            acc[f][0] += ar0*g00*(ti0 - tj00) + ar1*g10*(ti0 - tj10);
            acc[f][1] += ar0*g01*(ti1 - tj01) + ar1*g11*(ti1 - tj11);
        }

        asm volatile("cp.async.wait_group 0;\n");
        __syncthreads();
    }

    // ---- reduce over the 8 row-groups ----
    #pragma unroll
    for (int f = 0; f < 4; f++)
        #pragma unroll
        for (int e = 0; e < 2; e++) {
            float v = acc[f][e];
            v += __shfl_xor_sync(~0u, v, 4);
            v += __shfl_xor_sync(~0u, v, 8);
            v += __shfl_xor_sync(~0u, v, 16);
            acc[f][e] = v;
        }
    if (grp == 0) {
        #pragma unroll
        for (int f = 0; f < 4; f++) {
            int d0 = warpD + 8*f + 2*T;
            outp[(b*NN+i)*DD + d0]   = sm_ti[d0]   - acc[f][0];
            outp[(b*NN+i)*DD + d0+1] = sm_ti[d0+1] - acc[f][1];
        }
    }
}

// ---------------- launch ----------------
extern "C" void kernel_launch(void* const* d_in, const int* in_sizes, int n_in,
                              void* d_out, int out_size) {
    const float* t  = (const float*)d_in[0];
    const float* Qd = (const float*)d_in[1];
    const float* Kd = (const float*)d_in[2];
    const float* Vd = (const float*)d_in[3];
    const float* Qs = (const float*)d_in[4];
    const float* Ks = (const float*)d_in[5];
    const float* al = (const float*)d_in[6];
    const float* bl = (const float*)d_in[7];
    float* outp = (float*)d_out;

    dim3 grid48(NN/8, BB);
    dim3 gridBN(NN, BB);
    k1_proj<<<grid48, 384>>>(t, Qd, Kd, Qs, Ks, Vd);
    k2_sim<<<grid48, 384>>>();
    k3_m<<<grid48, 384>>>(al, bl);
    k5_heavy<<<gridBN, 256>>>(t, al, bl, outp);
}

// round 16
// speedup vs baseline: 3.5267x; 1.8835x over previous
#include <cuda_runtime.h>
#include <cuda_bf16.h>
#include <cstdint>

#define BB 2
#define NN 384
#define DD 256
#define DDIRC 128
#define DSIMC 64
#define EPSF 1e-6f
#define DELTAF 1e-6f
#define NT 24                 // NN/16 tiles
#define NPAIR (NT*(NT+1)/2)   // 300 tile-pair jobs per batch

// ---------------- scratch (static device globals; no allocations) ----------------
__device__ float g_q [BB*NN*DSIMC];
__device__ float g_k [BB*NN*DSIMC];
__device__ float g_qd[BB*NN*DDIRC];
__device__ float g_kd[BB*NN*DDIRC];
__device__ float g_s [BB*NN*NN];      // after k4: holds A = sigmoid(s_tilde)
__device__ float g_m [BB*NN];
__device__ float g_rinv[BB*NN];
__device__ double g_stats[BB*2];
__device__ __nv_bfloat16 g_vdt[DD*DDIRC];   // Vdt[d][r] = Vd[r][d], bf16
__device__ float g_part[BB*NT*NN*DD];       // 18.9MB partial sums

__device__ __forceinline__ uint32_t smem_u32(const void* p) {
    return (uint32_t)__cvta_generic_to_shared(p);
}
__device__ __forceinline__ void cp16(uint32_t dst, const float* src) {
    asm volatile("cp.async.cg.shared.global [%0], [%1], 16;\n" :: "r"(dst), "l"(src));
}
__device__ __forceinline__ float rcp_fast(float x) {
    float r; asm("rcp.approx.f32 %0, %1;" : "=f"(r) : "f"(x)); return r;
}
__device__ __forceinline__ float ex2_fast(float x) {
    float r; asm("ex2.approx.f32 %0, %1;" : "=f"(r) : "f"(x)); return r;
}

// ---------------- K1: projections (8 rows/block) + merged init ----------------
__global__ void k1_proj(const float* __restrict__ t,
                        const float* __restrict__ Qd, const float* __restrict__ Kd,
                        const float* __restrict__ Qs, const float* __restrict__ Ks,
                        const float* __restrict__ Vd) {
    const int b = blockIdx.y, n0 = blockIdx.x * 8;
    const int tid = threadIdx.x;                 // 384 threads

    if (b == 0) {
        for (int i = blockIdx.x * 384 + tid; i < DD*DDIRC; i += 48*384) {
            int d = i / DDIRC, r = i % DDIRC;
            g_vdt[i] = __float2bfloat16(Vd[r*DD + d]);
        }
        if (blockIdx.x == 0 && tid < BB*2) g_stats[tid] = 0.0;
    }

    __shared__ float ts[8*DD];
    for (int idx = tid; idx < 8*DD; idx += 384)
        ts[idx] = t[(b*NN + n0 + (idx >> 8))*DD + (idx & 255)];
    __syncthreads();

    const float* W; int ld, col; float* outp; int ostride;
    if (tid < 64)       { W = Qs; ld = DSIMC; col = tid;     outp = &g_q [(b*NN+n0)*DSIMC + col]; ostride = DSIMC; }
    else if (tid < 128) { W = Ks; ld = DSIMC; col = tid-64;  outp = &g_k [(b*NN+n0)*DSIMC + col]; ostride = DSIMC; }
    else if (tid < 256) { W = Qd; ld = DDIRC; col = tid-128; outp = &g_qd[(b*NN+n0)*DDIRC + col]; ostride = DDIRC; }
    else                { W = Kd; ld = DDIRC; col = tid-256; outp = &g_kd[(b*NN+n0)*DDIRC + col]; ostride = DDIRC; }

    float acc[8] = {};
    #pragma unroll 4
    for (int r = 0; r < DD; r++) {
        float w = W[r*ld + col];
        #pragma unroll
        for (int m = 0; m < 8; m++) acc[m] += ts[m*DD + r] * w;
    }
    #pragma unroll
    for (int m = 0; m < 8; m++) outp[m*ostride] = acc[m];
}

// ---------------- K2: symmetrized s + off-diagonal stats (8 rows/block) ----------------
__global__ void k2_sim() {
    const int b = blockIdx.y, i0 = blockIdx.x * 8, j = threadIdx.x;   // 384 threads
    __shared__ float4 qi[8][16], ki[8][16];
    __shared__ float red0[12], red1[12];
    for (int idx = j; idx < 128; idx += 384) {
        int m = idx >> 4, r4 = idx & 15;
        qi[m][r4] = ((const float4*)&g_q[(b*NN + i0 + m)*DSIMC])[r4];
        ki[m][r4] = ((const float4*)&g_k[(b*NN + i0 + m)*DSIMC])[r4];
    }
    __syncthreads();

    const float4* kj = (const float4*)&g_k[(b*NN+j)*DSIMC];
    const float4* qj = (const float4*)&g_q[(b*NN+j)*DSIMC];
    float acc[8] = {};
    #pragma unroll
    for (int r4 = 0; r4 < 16; r4++) {
        float4 kv = kj[r4], qv = qj[r4];
        #pragma unroll
        for (int m = 0; m < 8; m++) {
            float4 q4 = qi[m][r4], k4 = ki[m][r4];
            acc[m] += q4.x*kv.x + q4.y*kv.y + q4.z*kv.z + q4.w*kv.w
                    + k4.x*qv.x + k4.y*qv.y + k4.z*qv.z + k4.w*qv.w;
        }
    }
    float sv = 0.f, s2 = 0.f;
    #pragma unroll
    for (int m = 0; m < 8; m++) {
        float s = acc[m] * 0.0625f;   // 0.5 / sqrt(64)
        g_s[(b*NN + i0 + m)*NN + j] = s;
        float v = (j == i0 + m) ? 0.f : s;
        sv += v; s2 += v*v;
    }
    #pragma unroll
    for (int o = 16; o; o >>= 1) {
        sv += __shfl_xor_sync(~0u, sv, o);
        s2 += __shfl_xor_sync(~0u, s2, o);
    }
    int w = j >> 5, l = j & 31;
    if (!l) { red0[w] = sv; red1[w] = s2; }
    __syncthreads();
    if (j == 0) {
        double a = 0, c = 0;
        for (int w2 = 0; w2 < 12; w2++) { a += (double)red0[w2]; c += (double)red1[w2]; }
        atomicAdd(&g_stats[b*2+0], a);
        atomicAdd(&g_stats[b*2+1], c);
    }
}

// ---------------- K3: per-row exp-sum -> m (8 rows/block) ----------------
__global__ void k3_m(const float* __restrict__ al, const float* __restrict__ bl) {
    const int b = blockIdx.y, i0 = blockIdx.x * 8, j = threadIdx.x;   // 384 threads
    __shared__ float red[12][8];
    const float cnt = (float)(NN*(NN-1));
    float mu  = (float)(g_stats[b*2+0] / cnt);
    float var = (float)(g_stats[b*2+1] / cnt) - mu*mu;
    float inv = rsqrtf(var + EPSF);
    float a = al[0], bv = bl[0];
    float e[8];
    #pragma unroll
    for (int m = 0; m < 8; m++) {
        float s = g_s[(b*NN + i0 + m)*NN + j];
        e[m] = __expf(a * ((s - mu) * inv) + bv);   // GAMMA = 1
    }
    #pragma unroll
    for (int m = 0; m < 8; m++)
        #pragma unroll
        for (int o = 16; o; o >>= 1) e[m] += __shfl_xor_sync(~0u, e[m], o);
    int w = j >> 5, l = j & 31;
    if (!l) {
        #pragma unroll
        for (int m = 0; m < 8; m++) red[w][m] = e[m];
    }
    __syncthreads();
    if (j < 8) {
        float E = 0.f;
        for (int w2 = 0; w2 < 12; w2++) E += red[w2][j];
        g_m[b*NN + i0 + j] = 1.f / (E + EPSF);
    }
}

// ---------------- K4: A = sigmoid(s_tilde) in-place, row-sums of w -> g_rinv ----------------
__global__ void k4_rowsum(const float* __restrict__ al, const float* __restrict__ bl) {
    const int b = blockIdx.y, i0 = blockIdx.x * 8, j = threadIdx.x;   // 384 threads
    __shared__ float red[12][8];
    const float cnt = (float)(NN*(NN-1));
    float mu  = (float)(g_stats[b*2+0] / cnt);
    float var = (float)(g_stats[b*2+1] / cnt) - mu*mu;
    float inv = rsqrtf(var + EPSF);
    float a = al[0], bv = bl[0];
    float mj = g_m[b*NN + j];
    float acc[8];
    #pragma unroll
    for (int m = 0; m < 8; m++) {
        float s  = g_s[(b*NN + i0 + m)*NN + j];
        float ts = a * ((s - mu) * inv) + bv;
        float A  = 1.f / (1.f + __expf(-ts));
        g_s[(b*NN + i0 + m)*NN + j] = A;      // overwrite with A
        acc[m] = A * mj;                       // w_ij = A_ij * m_j (diagonal included)
    }
    #pragma unroll
    for (int m = 0; m < 8; m++)
        #pragma unroll
        for (int o = 16; o; o >>= 1) acc[m] += __shfl_xor_sync(~0u, acc[m], o);
    int w = j >> 5, l = j & 31;
    if (!l) {
        #pragma unroll
        for (int m = 0; m < 8; m++) red[w][m] = acc[m];
    }
    __syncthreads();
    if (j < 8) {
        float E = 0.f;
        for (int w2 = 0; w2 < 12; w2++) E += red[w2][j];
        g_rinv[b*NN + i0 + j] = 1.f / (E + DELTAF);
    }
}

// ---------------- K5: tile-pair jobs, both orientations per MMA ----------------
// smem layout (floats):
#define SM_T_OFF   0
#define SM_QD_OFF  (32*260)
#define SM_KD_OFF  (SM_QD_OFF + 32*132)
#define SM_AIJ_OFF (SM_KD_OFF + 32*132)
#define SM_AJI_OFF (SM_AIJ_OFF + 256)
#define SM_U_OFF   (SM_AJI_OFF + 256)
#define K5_SMEM_FLOATS (SM_U_OFF + (2*16*136)/2)
#define K5_SMEM_BYTES  (K5_SMEM_FLOATS*4)      // 77824

__global__ void __launch_bounds__(256, 2) k5_pair(const float* __restrict__ t) {
    extern __shared__ float sm[];
    float* sm_t   = sm + SM_T_OFF;
    float* sm_qd  = sm + SM_QD_OFF;
    float* sm_kd  = sm + SM_KD_OFF;
    float* sm_aIJ = sm + SM_AIJ_OFF;
    float* sm_aJI = sm + SM_AJI_OFF;
    __nv_bfloat16* sm_U = (__nv_bfloat16*)(sm + SM_U_OFF);

    const int b = blockIdx.y;
    int p = blockIdx.x, I = 0;
    while (p >= NT - I) { p -= NT - I; I++; }
    const int J = I + p;
    const bool diag = (I == J);

    const int tid = threadIdx.x;
    const int lane = tid & 31, wid = tid >> 5;
    const int T = lane & 3, grp = lane >> 2;
    const int warpD = wid * 32;

    // ---- async loads: 32 rows of t (I then J), qd, kd ----
    for (int c = tid; c < 2048; c += 256) {
        int row = c >> 6, ch = c & 63;
        int grow = (row < 16) ? (I*16 + row) : (J*16 + row - 16);
        cp16(smem_u32(&sm_t[row*260 + ch*4]), &t[(b*NN + grow)*DD + ch*4]);
    }
    for (int c = tid; c < 1024; c += 256) {
        int row = c >> 5, ch = c & 31;
        int grow = (row < 16) ? (I*16 + row) : (J*16 + row - 16);
        cp16(smem_u32(&sm_qd[row*132 + ch*4]), &g_qd[(b*NN + grow)*DDIRC + ch*4]);
        cp16(smem_u32(&sm_kd[row*132 + ch*4]), &g_kd[(b*NN + grow)*DDIRC + ch*4]);
    }
    asm volatile("cp.async.commit_group;\n");

    // ---- alpha pairs (independent of async loads) ----
    {
        int li = tid >> 4, lj = tid & 15;
        int gi = I*16 + li, gj = J*16 + lj;
        float A = g_s[(b*NN + gi)*NN + gj];    // holds sigmoid A after k4 (symmetric)
        float aij = 0.f, aji = 0.f;
        if (gi != gj) {
            float A2 = A * A;
            aij = A2 * g_m[b*NN + gj] * g_rinv[b*NN + gi];
            aji = A2 * g_m[b*NN + gi] * g_rinv[b*NN + gj];
        }
        sm_aIJ[tid] = aij;
        sm_aJI[tid] = aji;
    }

    // ---- preload B fragments (Vd) into registers ----
    uint32_t breg[8][4][2];
    #pragma unroll
    for (int kc = 0; kc < 8; kc++)
        #pragma unroll
        for (int f = 0; f < 4; f++) {
            int n = warpD + 8*f + grp;
            const __nv_bfloat16* base = &g_vdt[n*DDIRC + kc*16 + 2*T];
            breg[kc][f][0] = *(const uint32_t*)(base);
            breg[kc][f][1] = *(const uint32_t*)(base + 8);
        }

    asm volatile("cp.async.wait_group 0;\n");
    __syncthreads();

    const int jj = tid >> 4, rb = (tid & 15) * 8;

    // ---- build U[0] for i=0 ----
    {
        const float4* qip = (const float4*)&sm_qd[0*132 + rb];
        const float4* kip = (const float4*)&sm_kd[0*132 + rb];
        const float4* kjp = (const float4*)&sm_kd[(16+jj)*132 + rb];
        const float4* qjp = (const float4*)&sm_qd[(16+jj)*132 + rb];
        float4 qi0 = qip[0], qi1 = qip[1], ki0 = kip[0], ki1 = kip[1];
        float4 kj0 = kjp[0], kj1 = kjp[1], qj0 = qjp[0], qj1 = qjp[1];
        __nv_bfloat162* ud = (__nv_bfloat162*)&sm_U[jj*136 + rb];
        ud[0] = __floats2bfloat162_rn(qi0.x*kj0.x - ki0.x*qj0.x, qi0.y*kj0.y - ki0.y*qj0.y);
        ud[1] = __floats2bfloat162_rn(qi0.z*kj0.z - ki0.z*qj0.z, qi0.w*kj0.w - ki0.w*qj0.w);
        ud[2] = __floats2bfloat162_rn(qi1.x*kj1.x - ki1.x*qj1.x, qi1.y*kj1.y - ki1.y*qj1.y);
        ud[3] = __floats2bfloat162_rn(qi1.z*kj1.z - ki1.z*qj1.z, qi1.w*kj1.w - ki1.w*qj1.w);
    }
    __syncthreads();

    float accJ[4][4] = {};

    #pragma unroll 1
    for (int i = 0; i < 16; i++) {
        const int cur = i & 1, nxt = cur ^ 1;

        // ---- MMA on current U buffer ----
        float cf[4][4] = {};
        #pragma unroll
        for (int kc = 0; kc < 8; kc++) {
            const __nv_bfloat16* u0 = &sm_U[cur*2176 + grp*136     + kc*16 + 2*T];
            const __nv_bfloat16* u1 = &sm_U[cur*2176 + (grp+8)*136 + kc*16 + 2*T];
            uint32_t a0 = *(const uint32_t*)(u0);
            uint32_t a1 = *(const uint32_t*)(u1);
            uint32_t a2 = *(const uint32_t*)(u0 + 8);
            uint32_t a3 = *(const uint32_t*)(u1 + 8);
            #pragma unroll
            for (int f = 0; f < 4; f++)
                asm volatile(
                    "mma.sync.aligned.m16n8k16.row.col.f32.bf16.bf16.f32 "
                    "{%0,%1,%2,%3}, {%4,%5,%6,%7}, {%8,%9}, {%0,%1,%2,%3};"
                    : "+f"(cf[f][0]), "+f"(cf[f][1]), "+f"(cf[f][2]), "+f"(cf[f][3])
                    : "r"(a0), "r"(a1), "r"(a2), "r"(a3),
                      "r"(breg[kc][f][0]), "r"(breg[kc][f][1]));
        }

        // ---- build U[nxt] for i+1 ----
        if (i < 15) {
            const float4* qip = (const float4*)&sm_qd[(i+1)*132 + rb];
            const float4* kip = (const float4*)&sm_kd[(i+1)*132 + rb];
            const float4* kjp = (const float4*)&sm_kd[(16+jj)*132 + rb];
            const float4* qjp = (const float4*)&sm_qd[(16+jj)*132 + rb];
            float4 qi0 = qip[0], qi1 = qip[1], ki0 = kip[0], ki1 = kip[1];
            float4 kj0 = kjp[0], kj1 = kjp[1], qj0 = qjp[0], qj1 = qjp[1];
            __nv_bfloat162* ud = (__nv_bfloat162*)&sm_U[nxt*2176 + jj*136 + rb];
            ud[0] = __floats2bfloat162_rn(qi0.x*kj0.x - ki0.x*qj0.x, qi0.y*kj0.y - ki0.y*qj0.y);
            ud[1] = __floats2bfloat162_rn(qi0.z*kj0.z - ki0.z*qj0.z, qi0.w*kj0.w - ki0.w*qj0.w);
            ud[2] = __floats2bfloat162_rn(qi1.x*kj1.x - ki1.x*qj1.x, qi1.y*kj1.y - ki1.y*qj1.y);
            ud[3] = __floats2bfloat162_rn(qi1.z*kj1.z - ki1.z*qj1.z, qi1.w*kj1.w - ki1.w*qj1.w);
        }

        // ---- epilogue: gates (4 per rcp), both orientations ----
        const float aIJ0 = sm_aIJ[i*16 + grp], aIJ1 = sm_aIJ[i*16 + grp + 8];
        const float aJI0 = sm_aJI[i*16 + grp], aJI1 = sm_aJI[i*16 + grp + 8];
        float accI[4][2] = {};
        #pragma unroll
        for (int f = 0; f < 4; f++) {
            const int d0 = warpD + 8*f + 2*T;
            float ti0 = sm_t[i*260 + d0],          ti1 = sm_t[i*260 + d0 + 1];
            float tj00 = sm_t[(16+grp)*260 + d0],  tj01 = sm_t[(16+grp)*260 + d0 + 1];
            float tj10 = sm_t[(16+grp+8)*260 + d0],tj11 = sm_t[(16+grp+8)*260 + d0 + 1];
            const float L2E = 1.44269504f;
            float e0 = ex2_fast(-cf[f][0]*L2E);
            float e1 = ex2_fast(-cf[f][1]*L2E);
            float e2 = ex2_fast(-cf[f][2]*L2E);
            float e3 = ex2_fast(-cf[f][3]*L2E);
            float a0 = 1.f+e0, a1 = 1.f+e1, a2 = 1.f+e2, a3 = 1.f+e3;
            float p01 = a0*a1, p23 = a2*a3;
            float P = rcp_fast(p01*p23);
            float g0 = (a1*p23)*P;   // sigmoid(cf[f][0])
            float g1 = (a0*p23)*P;
            float g2 = (p01*a3)*P;
            float g3 = (p01*a2)*P;
            float df, gd;
            df = ti0 - tj00; gd = g0*df; accI[f][0] += aIJ0*gd; accJ[f][0] += aJI0*(gd - df);
            df = ti1 - tj01; gd = g1*df; accI[f][1] += aIJ0*gd; accJ[f][1] += aJI0*(gd - df);
            df = ti0 - tj10; gd = g2*df; accI[f][0] += aIJ1*gd; accJ[f][2] += aJI1*(gd - df);
            df = ti1 - tj11; gd = g3*df; accI[f][1] += aIJ1*gd; accJ[f][3] += aJI1*(gd - df);
        }

        // ---- reduce accI over the 8 row-groups; store row I*16+i, slot J ----
        #pragma unroll
        for (int f = 0; f < 4; f++)
            #pragma unroll
            for (int e = 0; e < 2; e++) {
                float v = accI[f][e];
                v += __shfl_xor_sync(~0u, v, 4);
                v += __shfl_xor_sync(~0u, v, 8);
                v += __shfl_xor_sync(~0u, v, 16);
                accI[f][e] = v;
            }
        if (grp == 0) {
            int base = ((b*NT + J)*NN + (I*16 + i))*DD;
            #pragma unroll
            for (int f = 0; f < 4; f++) {
                int d0 = warpD + 8*f + 2*T;
                *(float2*)&g_part[base + d0] = make_float2(accI[f][0], accI[f][1]);
            }
        }
        __syncthreads();
    }

    // ---- J-side store (slot I, rows of J) ----
    if (!diag) {
        #pragma unroll
        for (int f = 0; f < 4; f++) {
            int d0 = warpD + 8*f + 2*T;
            int base0 = ((b*NT + I)*NN + (J*16 + grp))*DD + d0;
            int base1 = ((b*NT + I)*NN + (J*16 + grp + 8))*DD + d0;
            *(float2*)&g_part[base0] = make_float2(accJ[f][0], accJ[f][1]);
            *(float2*)&g_part[base1] = make_float2(accJ[f][2], accJ[f][3]);
        }
    }
}

// ---------------- K6: final reduce over 24 slots ----------------
__global__ void k6_final(const float* __restrict__ t, float* __restrict__ outp) {
    int idx = blockIdx.x*256 + threadIdx.x;
    int b = idx / (NN*DD), rd = idx - b*(NN*DD);
    const float* pp = &g_part[(b*NT)*NN*DD + rd];
    float s = 0.f;
    #pragma unroll
    for (int k = 0; k < NT; k++) s += pp[k*NN*DD];
    outp[idx] = t[idx] - s;
}

// ---------------- launch ----------------
extern "C" void kernel_launch(void* const* d_in, const int* in_sizes, int n_in,
                              void* d_out, int out_size) {
    const float* t  = (const float*)d_in[0];
    const float* Qd = (const float*)d_in[1];
    const float* Kd = (const float*)d_in[2];
    const float* Vd = (const float*)d_in[3];
    const float* Qs = (const float*)d_in[4];
    const float* Ks = (const float*)d_in[5];
    const float* al = (const float*)d_in[6];
    const float* bl = (const float*)d_in[7];
    float* outp = (float*)d_out;

    cudaFuncSetAttribute(k5_pair, cudaFuncAttributeMaxDynamicSharedMemorySize, K5_SMEM_BYTES);

    dim3 grid48(NN/8, BB);
    dim3 gridP(NPAIR, BB);
    k1_proj<<<grid48, 384>>>(t, Qd, Kd, Qs, Ks, Vd);
    k2_sim<<<grid48, 384>>>();
    k3_m<<<grid48, 384>>>(al, bl);
    k4_rowsum<<<grid48, 384>>>(al, bl);
    k5_pair<<<gridP, 256, K5_SMEM_BYTES>>>(t);
    k6_final<<<(BB*NN*DD)/256, 256>>>(t, outp);
}

// round 17
// speedup vs baseline: 3.6480x; 1.0344x over previous
#include <cuda_runtime.h>
#include <cuda_bf16.h>
#include <cstdint>

#define BB 2
#define NN 384
#define DD 256
#define DDIRC 128
#define DSIMC 64
#define EPSF 1e-6f
#define DELTAF 1e-6f
#define NT 24                 // NN/16 tiles
#define NPAIR (NT*(NT+1)/2)   // 300 tile-pair jobs per batch

typedef unsigned long long u64;

// ---------------- scratch (static device globals; no allocations) ----------------
__device__ float g_q [BB*NN*DSIMC];
__device__ float g_k [BB*NN*DSIMC];
__device__ float g_qd[BB*NN*DDIRC];
__device__ float g_kd[BB*NN*DDIRC];
__device__ float g_s [BB*NN*NN];      // after k3: holds A = sigmoid(s_tilde)
__device__ float g_m [BB*NN];
__device__ float g_rinv[BB*NN];
__device__ double g_stats[BB*2];
__device__ __nv_bfloat16 g_vdt[DD*DDIRC];   // Vdt[d][r] = -log2(e) * Vd[r][d], bf16
__device__ float g_part[BB*NT*NN*DD];       // 18.9MB partial sums

__device__ __forceinline__ uint32_t smem_u32(const void* p) {
    return (uint32_t)__cvta_generic_to_shared(p);
}
__device__ __forceinline__ void cp16(uint32_t dst, const float* src) {
    asm volatile("cp.async.cg.shared.global [%0], [%1], 16;\n" :: "r"(dst), "l"(src));
}
__device__ __forceinline__ float rcp_fast(float x) {
    float r; asm("rcp.approx.f32 %0, %1;" : "=f"(r) : "f"(x)); return r;
}
__device__ __forceinline__ float ex2_fast(float x) {
    float r; asm("ex2.approx.f32 %0, %1;" : "=f"(r) : "f"(x)); return r;
}
// ---- packed f32x2 ----
__device__ __forceinline__ u64 pk2(float lo, float hi) {
    u64 r; asm("mov.b64 %0, {%1, %2};" : "=l"(r) : "f"(lo), "f"(hi)); return r;
}
__device__ __forceinline__ void upk2(u64 v, float& lo, float& hi) {
    asm("mov.b64 {%0, %1}, %2;" : "=f"(lo), "=f"(hi) : "l"(v));
}
__device__ __forceinline__ u64 mul2(u64 a, u64 b) {
    u64 r; asm("mul.rn.f32x2 %0, %1, %2;" : "=l"(r) : "l"(a), "l"(b)); return r;
}
__device__ __forceinline__ u64 fma2(u64 a, u64 b, u64 c) {
    u64 r; asm("fma.rn.f32x2 %0, %1, %2, %3;" : "=l"(r) : "l"(a), "l"(b), "l"(c)); return r;
}

// ---------------- K1: projections (8 rows/block) + merged init ----------------
__global__ void k1_proj(const float* __restrict__ t,
                        const float* __restrict__ Qd, const float* __restrict__ Kd,
                        const float* __restrict__ Qs, const float* __restrict__ Ks,
                        const float* __restrict__ Vd) {
    const int b = blockIdx.y, n0 = blockIdx.x * 8;
    const int tid = threadIdx.x;                 // 384 threads

    if (b == 0) {
        const float NL2E = -1.44269504f;         // bake -log2(e) into Vd
        for (int i = blockIdx.x * 384 + tid; i < DD*DDIRC; i += 48*384) {
            int d = i / DDIRC, r = i % DDIRC;
            g_vdt[i] = __float2bfloat16(NL2E * Vd[r*DD + d]);
        }
        if (blockIdx.x == 0 && tid < BB*2) g_stats[tid] = 0.0;
    }

    __shared__ float ts[8*DD];
    for (int idx = tid; idx < 8*DD; idx += 384)
        ts[idx] = t[(b*NN + n0 + (idx >> 8))*DD + (idx & 255)];
    __syncthreads();

    const float* W; int ld, col; float* outp; int ostride;
    if (tid < 64)       { W = Qs; ld = DSIMC; col = tid;     outp = &g_q [(b*NN+n0)*DSIMC + col]; ostride = DSIMC; }
    else if (tid < 128) { W = Ks; ld = DSIMC; col = tid-64;  outp = &g_k [(b*NN+n0)*DSIMC + col]; ostride = DSIMC; }
    else if (tid < 256) { W = Qd; ld = DDIRC; col = tid-128; outp = &g_qd[(b*NN+n0)*DDIRC + col]; ostride = DDIRC; }
    else                { W = Kd; ld = DDIRC; col = tid-256; outp = &g_kd[(b*NN+n0)*DDIRC + col]; ostride = DDIRC; }

    float acc[8] = {};
    #pragma unroll 4
    for (int r = 0; r < DD; r++) {
        float w = W[r*ld + col];
        #pragma unroll
        for (int m = 0; m < 8; m++) acc[m] += ts[m*DD + r] * w;
    }
    #pragma unroll
    for (int m = 0; m < 8; m++) outp[m*ostride] = acc[m];
}

// ---------------- K2: symmetrized s + off-diagonal stats (4 rows/block) ----------------
__global__ void k2_sim() {
    const int b = blockIdx.y, i0 = blockIdx.x * 4, j = threadIdx.x;   // 384 threads
    __shared__ float4 qi[4][16], ki[4][16];
    __shared__ float red0[12], red1[12];
    if (j < 64) {
        int m = j >> 4, r4 = j & 15;
        qi[m][r4] = ((const float4*)&g_q[(b*NN + i0 + m)*DSIMC])[r4];
        ki[m][r4] = ((const float4*)&g_k[(b*NN + i0 + m)*DSIMC])[r4];
    }
    __syncthreads();

    const float4* kj = (const float4*)&g_k[(b*NN+j)*DSIMC];
    const float4* qj = (const float4*)&g_q[(b*NN+j)*DSIMC];
    float acc[4] = {};
    #pragma unroll
    for (int r4 = 0; r4 < 16; r4++) {
        float4 kv = kj[r4], qv = qj[r4];
        #pragma unroll
        for (int m = 0; m < 4; m++) {
            float4 q4 = qi[m][r4], k4 = ki[m][r4];
            acc[m] += q4.x*kv.x + q4.y*kv.y + q4.z*kv.z + q4.w*kv.w
                    + k4.x*qv.x + k4.y*qv.y + k4.z*qv.z + k4.w*qv.w;
        }
    }
    float sv = 0.f, s2 = 0.f;
    #pragma unroll
    for (int m = 0; m < 4; m++) {
        float s = acc[m] * 0.0625f;   // 0.5 / sqrt(64)
        g_s[(b*NN + i0 + m)*NN + j] = s;
        float v = (j == i0 + m) ? 0.f : s;
        sv += v; s2 += v*v;
    }
    #pragma unroll
    for (int o = 16; o; o >>= 1) {
        sv += __shfl_xor_sync(~0u, sv, o);
        s2 += __shfl_xor_sync(~0u, s2, o);
    }
    int w = j >> 5, l = j & 31;
    if (!l) { red0[w] = sv; red1[w] = s2; }
    __syncthreads();
    if (j == 0) {
        double a = 0, c = 0;
        for (int w2 = 0; w2 < 12; w2++) { a += (double)red0[w2]; c += (double)red1[w2]; }
        atomicAdd(&g_stats[b*2+0], a);
        atomicAdd(&g_stats[b*2+1], c);
    }
}

// ---------------- K3: fused A = sigmoid(s~) in-place + exp rowsum -> m (4 rows/block) ----
__global__ void k3_am(const float* __restrict__ al, const float* __restrict__ bl) {
    const int b = blockIdx.y, i0 = blockIdx.x * 4, j = threadIdx.x;   // 384 threads
    __shared__ float red[12][4];
    const float cnt = (float)(NN*(NN-1));
    float mu  = (float)(g_stats[b*2+0] / cnt);
    float var = (float)(g_stats[b*2+1] / cnt) - mu*mu;
    float inv = rsqrtf(var + EPSF);
    float a = al[0], bv = bl[0];
    float e[4];
    #pragma unroll
    for (int m = 0; m < 4; m++) {
        float s  = g_s[(b*NN + i0 + m)*NN + j];
        float ts = a * ((s - mu) * inv) + bv;
        float ev = __expf(ts);                         // GAMMA = 1
        g_s[(b*NN + i0 + m)*NN + j] = ev * rcp_fast(1.f + ev);  // A = sigmoid(ts)
        e[m] = ev;
    }
    #pragma unroll
    for (int m = 0; m < 4; m++)
        #pragma unroll
        for (int o = 16; o; o >>= 1) e[m] += __shfl_xor_sync(~0u, e[m], o);
    int w = j >> 5, l = j & 31;
    if (!l) {
        #pragma unroll
        for (int m = 0; m < 4; m++) red[w][m] = e[m];
    }
    __syncthreads();
    if (j < 4) {
        float E = 0.f;
        for (int w2 = 0; w2 < 12; w2++) E += red[w2][j];
        g_m[b*NN + i0 + j] = 1.f / (E + EPSF);
    }
}

// ---------------- K4: light rowsum of w = A*m_j -> rinv (4 rows/block) ----------------
__global__ void k4_rowsum() {
    const int b = blockIdx.y, i0 = blockIdx.x * 4, j = threadIdx.x;   // 384 threads
    __shared__ float red[12][4];
    float mj = g_m[b*NN + j];
    float acc[4];
    #pragma unroll
    for (int m = 0; m < 4; m++)
        acc[m] = g_s[(b*NN + i0 + m)*NN + j] * mj;   // diagonal included
    #pragma unroll
    for (int m = 0; m < 4; m++)
        #pragma unroll
        for (int o = 16; o; o >>= 1) acc[m] += __shfl_xor_sync(~0u, acc[m], o);
    int w = j >> 5, l = j & 31;
    if (!l) {
        #pragma unroll
        for (int m = 0; m < 4; m++) red[w][m] = acc[m];
    }
    __syncthreads();
    if (j < 4) {
        float E = 0.f;
        for (int w2 = 0; w2 < 12; w2++) E += red[w2][j];
        g_rinv[b*NN + i0 + j] = 1.f / (E + DELTAF);
    }
}

// ---------------- K5: tile-pair jobs, packed f32x2 epilogue ----------------
// smem layout (floats):
#define SM_T_OFF   0
#define SM_QD_OFF  (32*260)
#define SM_KD_OFF  (SM_QD_OFF + 32*132)
#define SM_AIJ_OFF (SM_KD_OFF + 32*132)
#define SM_AJI_OFF (SM_AIJ_OFF + 256)
#define SM_U_OFF   (SM_AJI_OFF + 256)
#define K5_SMEM_FLOATS (SM_U_OFF + (2*16*136)/2)
#define K5_SMEM_BYTES  (K5_SMEM_FLOATS*4)      // 77824

__global__ void __launch_bounds__(256, 2) k5_pair(const float* __restrict__ t) {
    extern __shared__ float sm[];
    float* sm_t   = sm + SM_T_OFF;
    float* sm_qd  = sm + SM_QD_OFF;
    float* sm_kd  = sm + SM_KD_OFF;
    float* sm_aIJ = sm + SM_AIJ_OFF;
    float* sm_aJI = sm + SM_AJI_OFF;   // stores NEGATED alpha_ji
    __nv_bfloat16* sm_U = (__nv_bfloat16*)(sm + SM_U_OFF);

    const int b = blockIdx.y;
    int p = blockIdx.x, I = 0;
    while (p >= NT - I) { p -= NT - I; I++; }
    const int J = I + p;
    const bool diag = (I == J);

    const int tid = threadIdx.x;
    const int lane = tid & 31, wid = tid >> 5;
    const int T = lane & 3, grp = lane >> 2;
    const int warpD = wid * 32;

    // ---- async loads: 32 rows of t (I then J), qd, kd ----
    for (int c = tid; c < 2048; c += 256) {
        int row = c >> 6, ch = c & 63;
        int grow = (row < 16) ? (I*16 + row) : (J*16 + row - 16);
        cp16(smem_u32(&sm_t[row*260 + ch*4]), &t[(b*NN + grow)*DD + ch*4]);
    }
    for (int c = tid; c < 1024; c += 256) {
        int row = c >> 5, ch = c & 31;
        int grow = (row < 16) ? (I*16 + row) : (J*16 + row - 16);
        cp16(smem_u32(&sm_qd[row*132 + ch*4]), &g_qd[(b*NN + grow)*DDIRC + ch*4]);
        cp16(smem_u32(&sm_kd[row*132 + ch*4]), &g_kd[(b*NN + grow)*DDIRC + ch*4]);
    }
    asm volatile("cp.async.commit_group;\n");

    // ---- alpha pairs (independent of async loads) ----
    {
        int li = tid >> 4, lj = tid & 15;
        int gi = I*16 + li, gj = J*16 + lj;
        float A = g_s[(b*NN + gi)*NN + gj];    // sigmoid A (symmetric)
        float aij = 0.f, aji = 0.f;
        if (gi != gj) {
            float A2 = A * A;
            aij = A2 * g_m[b*NN + gj] * g_rinv[b*NN + gi];
            aji = A2 * g_m[b*NN + gi] * g_rinv[b*NN + gj];
        }
        sm_aIJ[tid] = aij;
        sm_aJI[tid] = -aji;                    // negated
    }

    // ---- preload B fragments (Vd * -log2e) into registers ----
    uint32_t breg[8][4][2];
    #pragma unroll
    for (int kc = 0; kc < 8; kc++)
        #pragma unroll
        for (int f = 0; f < 4; f++) {
            int n = warpD + 8*f + grp;
            const __nv_bfloat16* base = &g_vdt[n*DDIRC + kc*16 + 2*T];
            breg[kc][f][0] = *(const uint32_t*)(base);
            breg[kc][f][1] = *(const uint32_t*)(base + 8);
        }

    asm volatile("cp.async.wait_group 0;\n");
    __syncthreads();

    // ---- negate J-half qd once (u = qi*kj + ki*(-qj)) ----
    for (int c = tid; c < 2048; c += 256) {
        int r = c >> 7, d = c & 127;
        sm_qd[(16+r)*132 + d] = -sm_qd[(16+r)*132 + d];
    }

    const int jj = tid >> 4, rb = (tid & 15) * 8;
    const u64 m1p = pk2(-1.f, -1.f);

    __syncthreads();

    // ---- build U[0] for i=0 ----
    {
        const u64* qip  = (const u64*)&sm_qd[0*132 + rb];
        const u64* kip  = (const u64*)&sm_kd[0*132 + rb];
        const u64* kjp  = (const u64*)&sm_kd[(16+jj)*132 + rb];
        const u64* nqjp = (const u64*)&sm_qd[(16+jj)*132 + rb];
        uint4 uc;
        uint32_t* ucp = (uint32_t*)&uc;
        #pragma unroll
        for (int pr = 0; pr < 4; pr++) {
            u64 u2 = fma2(kip[pr], nqjp[pr], mul2(qip[pr], kjp[pr]));
            float lo, hi; upk2(u2, lo, hi);
            __nv_bfloat162 cv = __floats2bfloat162_rn(lo, hi);
            ucp[pr] = *(uint32_t*)&cv;
        }
        *(uint4*)&sm_U[jj*136 + rb] = uc;
    }
    __syncthreads();

    u64 accJ0[4] = {}, accJ1[4] = {};

    #pragma unroll 1
    for (int i = 0; i < 16; i++) {
        const int cur = i & 1, nxt = cur ^ 1;

        // ---- MMA on current U buffer; output = -log2e * kappa ----
        float cf[4][4] = {};
        #pragma unroll
        for (int kc = 0; kc < 8; kc++) {
            const __nv_bfloat16* u0 = &sm_U[cur*2176 + grp*136     + kc*16 + 2*T];
            const __nv_bfloat16* u1 = &sm_U[cur*2176 + (grp+8)*136 + kc*16 + 2*T];
            uint32_t a0 = *(const uint32_t*)(u0);
            uint32_t a1 = *(const uint32_t*)(u1);
            uint32_t a2 = *(const uint32_t*)(u0 + 8);
            uint32_t a3 = *(const uint32_t*)(u1 + 8);
            #pragma unroll
            for (int f = 0; f < 4; f++)
                asm volatile(
                    "mma.sync.aligned.m16n8k16.row.col.f32.bf16.bf16.f32 "
                    "{%0,%1,%2,%3}, {%4,%5,%6,%7}, {%8,%9}, {%0,%1,%2,%3};"
                    : "+f"(cf[f][0]), "+f"(cf[f][1]), "+f"(cf[f][2]), "+f"(cf[f][3])
                    : "r"(a0), "r"(a1), "r"(a2), "r"(a3),
                      "r"(breg[kc][f][0]), "r"(breg[kc][f][1]));
        }

        // ---- build U[nxt] for i+1 ----
        if (i < 15) {
            const u64* qip  = (const u64*)&sm_qd[(i+1)*132 + rb];
            const u64* kip  = (const u64*)&sm_kd[(i+1)*132 + rb];
            const u64* kjp  = (const u64*)&sm_kd[(16+jj)*132 + rb];
            const u64* nqjp = (const u64*)&sm_qd[(16+jj)*132 + rb];
            uint4 uc;
            uint32_t* ucp = (uint32_t*)&uc;
            #pragma unroll
            for (int pr = 0; pr < 4; pr++) {
                u64 u2 = fma2(kip[pr], nqjp[pr], mul2(qip[pr], kjp[pr]));
                float lo, hi; upk2(u2, lo, hi);
                __nv_bfloat162 cv = __floats2bfloat162_rn(lo, hi);
                ucp[pr] = *(uint32_t*)&cv;
            }
            *(uint4*)&sm_U[nxt*2176 + jj*136 + rb] = uc;
        }

        // ---- epilogue: e = ex2(cf) directly; g = 1/(1+e); 1-g = e*g ----
        const float aIJ0 = sm_aIJ[i*16 + grp], aIJ1 = sm_aIJ[i*16 + grp + 8];
        const float nJI0 = sm_aJI[i*16 + grp], nJI1 = sm_aJI[i*16 + grp + 8];
        const u64 aIJ0p = pk2(aIJ0, aIJ0), aIJ1p = pk2(aIJ1, aIJ1);
        const u64 nJI0p = pk2(nJI0, nJI0), nJI1p = pk2(nJI1, nJI1);
        u64 accI[4];
        #pragma unroll
        for (int f = 0; f < 4; f++) {
            const int d0 = warpD + 8*f + 2*T;
            u64 ti2 = *(const u64*)&sm_t[i*260 + d0];
            u64 tj0 = *(const u64*)&sm_t[(16+grp)*260 + d0];
            u64 tj1 = *(const u64*)&sm_t[(16+grp+8)*260 + d0];
            float e0 = ex2_fast(cf[f][0]);
            float e1 = ex2_fast(cf[f][1]);
            float e2 = ex2_fast(cf[f][2]);
            float e3 = ex2_fast(cf[f][3]);
            float a0 = 1.f+e0, a1 = 1.f+e1, a2 = 1.f+e2, a3 = 1.f+e3;
            float p01 = a0*a1, p23 = a2*a3;
            float P = rcp_fast(p01*p23);
            float q01 = p23*P, q23 = p01*P;
            u64 g01 = pk2(a1*q01, a0*q01);     // (sig(k0), sig(k1))
            u64 g23 = pk2(a3*q23, a2*q23);
            u64 e01 = pk2(e0, e1), e23 = pk2(e2, e3);
            u64 df0 = fma2(tj0, m1p, ti2);     // t_i - t_j
            u64 df1 = fma2(tj1, m1p, ti2);
            u64 gd0 = mul2(g01, df0);
            u64 gd1 = mul2(g23, df1);
            accI[f]  = fma2(aIJ1p, gd1, fma2(aIJ0p, gd0, pk2(0.f, 0.f)));
            accJ0[f] = fma2(nJI0p, mul2(e01, gd0), accJ0[f]);
            accJ1[f] = fma2(nJI1p, mul2(e23, gd1), accJ1[f]);
        }

        // ---- reduce accI over the 8 row-groups; store row I*16+i, slot J ----
        float rI[4][2];
        #pragma unroll
        for (int f = 0; f < 4; f++) {
            upk2(accI[f], rI[f][0], rI[f][1]);
            #pragma unroll
            for (int e = 0; e < 2; e++) {
                float v = rI[f][e];
                v += __shfl_xor_sync(~0u, v, 4);
                v += __shfl_xor_sync(~0u, v, 8);
                v += __shfl_xor_sync(~0u, v, 16);
                rI[f][e] = v;
            }
        }
        if (grp == 0) {
            int base = ((b*NT + J)*NN + (I*16 + i))*DD;
            #pragma unroll
            for (int f = 0; f < 4; f++) {
                int d0 = warpD + 8*f + 2*T;
                *(float2*)&g_part[base + d0] = make_float2(rI[f][0], rI[f][1]);
            }
        }
        __syncthreads();
    }

    // ---- J-side store (slot I, rows of J) ----
    if (!diag) {
        #pragma unroll
        for (int f = 0; f < 4; f++) {
            int d0 = warpD + 8*f + 2*T;
            float j00, j01, j10, j11;
            upk2(accJ0[f], j00, j01);
            upk2(accJ1[f], j10, j11);
            int base0 = ((b*NT + I)*NN + (J*16 + grp))*DD + d0;
            int base1 = ((b*NT + I)*NN + (J*16 + grp + 8))*DD + d0;
            *(float2*)&g_part[base0] = make_float2(j00, j01);
            *(float2*)&g_part[base1] = make_float2(j10, j11);
        }
    }
}

// ---------------- K6: final reduce over 24 slots (float4) ----------------
__global__ void k6_final(const float* __restrict__ t, float* __restrict__ outp) {
    int idx4 = blockIdx.x*256 + threadIdx.x;           // over BB*NN*DD/4
    const int per_b = NN*DD/4;
    int b = idx4 / per_b, rd4 = idx4 - b*per_b;
    const float4* pp = (const float4*)g_part + (size_t)(b*NT)*per_b + rd4;
    float4 s = make_float4(0.f, 0.f, 0.f, 0.f);
    #pragma unroll
    for (int k = 0; k < NT; k++) {
        float4 v = pp[(size_t)k*per_b];
        s.x += v.x; s.y += v.y; s.z += v.z; s.w += v.w;
    }
    float4 tv = ((const float4*)t)[idx4];
    ((float4*)outp)[idx4] = make_float4(tv.x - s.x, tv.y - s.y, tv.z - s.z, tv.w - s.w);
}

// ---------------- launch ----------------
extern "C" void kernel_launch(void* const* d_in, const int* in_sizes, int n_in,
                              void* d_out, int out_size) {
    const float* t  = (const float*)d_in[0];
    const float* Qd = (const float*)d_in[1];
    const float* Kd = (const float*)d_in[2];
    const float* Vd = (const float*)d_in[3];
    const float* Qs = (const float*)d_in[4];
    const float* Ks = (const float*)d_in[5];
    const float* al = (const float*)d_in[6];
    const float* bl = (const float*)d_in[7];
    float* outp = (float*)d_out;

    cudaFuncSetAttribute(k5_pair, cudaFuncAttributeMaxDynamicSharedMemorySize, K5_SMEM_BYTES);

    dim3 grid48(NN/8, BB);
    dim3 grid96(NN/4, BB);
    dim3 gridP(NPAIR, BB);
    k1_proj<<<grid48, 384>>>(t, Qd, Kd, Qs, Ks, Vd);
    k2_sim<<<grid96, 384>>>();
    k3_am<<<grid96, 384>>>(al, bl);
    k4_rowsum<<<grid96, 384>>>();
    k5_pair<<<gridP, 256, K5_SMEM_BYTES>>>(t);
    k6_final<<<(BB*NN*DD/4)/256, 256>>>(t, outp);
}